// round 13
// baseline (speedup 1.0000x reference)
#include <cuda_runtime.h>
#include <math.h>
#include <stdint.h>

#define HW    4096
#define CDIM  256
#define BATCH 8
#define NBH   64     // B*HEADS
#define DH    64     // DIM_HEAD

// ---------------- scratch (device globals; no runtime allocation) ----------
__device__ float g_ctx[BATCH * CDIM * HW];        // layernormed context (tf32-rounded)
__device__ float g_qs [BATCH * CDIM * HW];        // layernormed query_source (tf32-rounded)
__device__ float g_kv [BATCH * 1024 * HW];        // w_kv output (K l2-normed, V raw)
__device__ float g_q  [BATCH * 512  * HW];        // w_q output (l2-normalized)
__device__ float g_att[BATCH * 512  * HW];        // attention output (tf32-rounded)
__device__ float g_qprobe[NBH * DH];
__device__ float g_rowabs[NBH * DH * 64];         // [bh][d][h]
__device__ float g_colabs[NBH * DH * 64];         // [bh][d][w]
__device__ int   g_idxh[NBH * 8];
__device__ int   g_idxw[NBH * 8];
__device__ float g_kselT[NBH * 64 * DH];          // [bh][d][j]  (K^T for mma)
__device__ float g_vsel [NBH * 64 * DH];          // [bh][j][d]

// tf32-pre-rounded weights, packed in mma-fragment order:
// [mtile128][kt16][mblk16][ks8][lane32] -> float4 {A[m][k],A[m+8][k],A[m][k+4],A[m+8][k+4]}
__device__ float g_wkvp[1024 * 256];
__device__ float g_wqp [512 * 256];
__device__ float g_woutp[256 * 512];

__device__ __forceinline__ float tf32r(float x) {
    uint32_t u;
    asm("cvt.rna.tf32.f32 %0, %1;" : "=r"(u) : "f"(x));
    return __uint_as_float(u);
}

// ---------------- zero scratch reductions ----------------------------------
__global__ void zero_kernel() {
    int i = blockIdx.x * 256 + threadIdx.x;
    if (i < NBH * DH) g_qprobe[i] = 0.f;
    if (i < NBH * DH * 64) { g_rowabs[i] = 0.f; g_colabs[i] = 0.f; }
}

// ---------------- weight prep: tf32-round + pack into fragment order -------
__global__ void prep_w(const float* __restrict__ wkv,
                       const float* __restrict__ wq,
                       const float* __restrict__ wout) {
    int fid = blockIdx.x * 256 + threadIdx.x;
    const float* W; float4* Dst; int K, rel;
    if (fid < 65536)      { W = wkv;  Dst = (float4*)g_wkvp;  K = 256; rel = fid; }
    else if (fid < 98304) { W = wq;   Dst = (float4*)g_wqp;   K = 256; rel = fid - 65536; }
    else                  { W = wout; Dst = (float4*)g_woutp; K = 512; rel = fid - 98304; }
    int KT = K >> 4;
    int per_mtile = KT * 512;
    int mtile = rel / per_mtile;
    int r2 = rel - mtile * per_mtile;
    int kt = r2 >> 9;
    int sub = r2 & 511;
    int mblk = (sub >> 6) & 7;
    int ks = (sub >> 5) & 1;
    int lane = sub & 31;
    int gid = lane >> 2, tq = lane & 3;
    int m = mtile * 128 + mblk * 16 + gid;
    int k = kt * 16 + ks * 8 + tq;
    float4 v;
    v.x = tf32r(W[(size_t)m * K + k]);
    v.y = tf32r(W[(size_t)(m + 8) * K + k]);
    v.z = tf32r(W[(size_t)m * K + k + 4]);
    v.w = tf32r(W[(size_t)(m + 8) * K + k + 4]);
    Dst[rel] = v;
}

// ---------------- channel layernorm (scalar, round-6 numerics) -------------
__global__ void ln_kernel(const float* __restrict__ x,
                          const float* __restrict__ gw,
                          const float* __restrict__ bw,
                          int outsel) {
    float* out = outsel ? g_qs : g_ctx;
    int tx = threadIdx.x, ty = threadIdx.y;
    int gp = blockIdx.x * 32 + tx;
    int bidx = gp >> 12;
    int p = gp & (HW - 1);
    size_t base = (size_t)bidx * CDIM * HW + p;

    float vals[32];
    float s = 0.f, s2 = 0.f;
#pragma unroll
    for (int i = 0; i < 32; i++) {
        int c = ty + i * 8;
        float v = x[base + (size_t)c * HW];
        vals[i] = v; s += v; s2 += v * v;
    }
    __shared__ float rs[8][32], rs2[8][32];
    rs[ty][tx] = s; rs2[ty][tx] = s2;
    __syncthreads();
    for (int st = 4; st > 0; st >>= 1) {
        if (ty < st) { rs[ty][tx] += rs[ty + st][tx]; rs2[ty][tx] += rs2[ty + st][tx]; }
        __syncthreads();
    }
    float mean = rs[0][tx] * (1.0f / CDIM);
    float var  = rs2[0][tx] * (1.0f / CDIM) - mean * mean;
    float inv  = rsqrtf(var + 1e-5f);
#pragma unroll
    for (int i = 0; i < 32; i++) {
        int c = ty + i * 8;
        out[base + (size_t)c * HW] = tf32r((vals[i] - mean) * inv * gw[c] + bw[c]);
    }
}

// ---------------- cp.async helpers -----------------------------------------
__device__ __forceinline__ void cpasync16(uint32_t smem, const void* g) {
    asm volatile("cp.async.cg.shared.global [%0], [%1], 16;\n" :: "r"(smem), "l"(g));
}
#define CP_COMMIT() asm volatile("cp.async.commit_group;\n" ::: "memory")
#define CP_WAIT2()  asm volatile("cp.async.wait_group 2;\n" ::: "memory")

// ---------------- tensor-core GEMM: fused kv + q (sel=3) -------------------
// 128 threads / 4 warps (2x2), 64x64 warp tiles, 128x128 block tile, 4-stage.
// Per-output-element MMA sequence identical to prior rounds.
#define BS_STRIDE 136   // 128 + 8 pad (conflict-free B fragment loads)

__global__ void __launch_bounds__(128)
tgemm_kernel(int K, int sel) {
    int by = blockIdx.y;
    int selEff = sel;
    if (sel == 3) {
        if (by < 8) selEff = 0;
        else { selEff = 1; by -= 8; }
    }
    const uint4* Ap4; const float* Bp; float* Cp;
    if (selEff == 0) { Ap4 = (const uint4*)g_wkvp; Bp = g_ctx; Cp = g_kv; }
    else             { Ap4 = (const uint4*)g_wqp;  Bp = g_qs;  Cp = g_q;  }
    int KT = K >> 4;
    Bp += (size_t)blockIdx.z * K * HW;
    Cp += (size_t)blockIdx.z * ((selEff == 0) ? 1024 : 512) * HW;
    Ap4 += (size_t)by * (KT * 512);

    __shared__ __align__(16) uint4 As4[4][512];
    __shared__ __align__(16) float Bs[4][16][BS_STRIDE];

    int m0 = by * 128, n0 = blockIdx.x * 128;
    int tid = threadIdx.x;
    int wid = tid >> 5, lane = tid & 31;
    int wm = wid >> 1, wn = wid & 1;          // warp 2x2, 64x64 tiles
    int gid = lane >> 2, tq = lane & 3;

    int bk = tid >> 3;            // 0..15
    int bn = (tid & 7) * 16;      // 0..112

    auto load_stage = [&](int s, int kt) {
#pragma unroll
        for (int r = 0; r < 4; r++) {
            uint32_t adst = (uint32_t)__cvta_generic_to_shared(&As4[s][tid + r * 128]);
            cpasync16(adst, Ap4 + kt * 512 + tid + r * 128);
        }
        uint32_t bdst = (uint32_t)__cvta_generic_to_shared(&Bs[s][bk][bn]);
        const float* bsrc = Bp + (size_t)(kt * 16 + bk) * HW + n0 + bn;
#pragma unroll
        for (int r = 0; r < 4; r++)
            cpasync16(bdst + r * 16, bsrc + r * 4);
    };

    float acc[4][8][4];
#pragma unroll
    for (int i = 0; i < 4; i++)
#pragma unroll
        for (int n = 0; n < 8; n++)
#pragma unroll
            for (int r = 0; r < 4; r++) acc[i][n][r] = 0.f;

    load_stage(0, 0); CP_COMMIT();
    load_stage(1, 1); CP_COMMIT();
    load_stage(2, 2); CP_COMMIT();

    for (int kt = 0; kt < KT; kt++) {
        CP_WAIT2();
        __syncthreads();
        if (kt + 3 < KT) load_stage((kt + 3) & 3, kt + 3);
        CP_COMMIT();
        int s = kt & 3;

#pragma unroll
        for (int ks = 0; ks < 2; ks++) {
            int kk = ks * 8 + tq;
            uint4 af[4];
            uint32_t bf[8][2];
#pragma unroll
            for (int i = 0; i < 4; i++)
                af[i] = As4[s][(4 * wm + i) * 64 + ks * 32 + lane];
#pragma unroll
            for (int n = 0; n < 8; n++) {
                int c = wn * 64 + n * 8 + gid;
                bf[n][0] = __float_as_uint(Bs[s][kk][c]);
                bf[n][1] = __float_as_uint(Bs[s][kk + 4][c]);
            }
#pragma unroll
            for (int i = 0; i < 4; i++)
#pragma unroll
                for (int n = 0; n < 8; n++) {
                    asm volatile(
                        "mma.sync.aligned.m16n8k8.row.col.f32.tf32.tf32.f32 "
                        "{%0,%1,%2,%3}, {%4,%5,%6,%7}, {%8,%9}, {%0,%1,%2,%3};"
                        : "+f"(acc[i][n][0]), "+f"(acc[i][n][1]),
                          "+f"(acc[i][n][2]), "+f"(acc[i][n][3])
                        : "r"(af[i].x), "r"(af[i].y), "r"(af[i].z), "r"(af[i].w),
                          "r"(bf[n][0]), "r"(bf[n][1]));
                }
        }
    }

    bool fuse = (selEff == 1) || (selEff == 0 && by < 4);
    if (fuse) {
        // l2-normalize over d per pixel column (warp holds all 64 d of its head)
        float inv_c[8][2];
#pragma unroll
        for (int n = 0; n < 8; n++) {
            float s0 = 0.f, s1 = 0.f;
#pragma unroll
            for (int i = 0; i < 4; i++) {
                s0 += acc[i][n][0] * acc[i][n][0] + acc[i][n][2] * acc[i][n][2];
                s1 += acc[i][n][1] * acc[i][n][1] + acc[i][n][3] * acc[i][n][3];
            }
            s0 += __shfl_xor_sync(0xffffffffu, s0, 4);
            s0 += __shfl_xor_sync(0xffffffffu, s0, 8);
            s0 += __shfl_xor_sync(0xffffffffu, s0, 16);
            s1 += __shfl_xor_sync(0xffffffffu, s1, 4);
            s1 += __shfl_xor_sync(0xffffffffu, s1, 8);
            s1 += __shfl_xor_sync(0xffffffffu, s1, 16);
            inv_c[n][0] = 1.0f / fmaxf(sqrtf(s0), 1e-12f);
            inv_c[n][1] = 1.0f / fmaxf(sqrtf(s1), 1e-12f);
        }
#pragma unroll
        for (int i = 0; i < 4; i++)
#pragma unroll
            for (int n = 0; n < 8; n++) {
                acc[i][n][0] *= inv_c[n][0];
                acc[i][n][1] *= inv_c[n][1];
                acc[i][n][2] *= inv_c[n][0];
                acc[i][n][3] *= inv_c[n][1];
            }

        int head = by * 2 + wm;
        int bh = blockIdx.z * 8 + head;

        if (selEff == 1) {
#pragma unroll
            for (int i = 0; i < 4; i++) {
                float r0s = 0.f, r1s = 0.f;
#pragma unroll
                for (int n = 0; n < 8; n++) {
                    r0s += acc[i][n][0] + acc[i][n][1];
                    r1s += acc[i][n][2] + acc[i][n][3];
                }
                r0s += __shfl_xor_sync(0xffffffffu, r0s, 1);
                r0s += __shfl_xor_sync(0xffffffffu, r0s, 2);
                r1s += __shfl_xor_sync(0xffffffffu, r1s, 1);
                r1s += __shfl_xor_sync(0xffffffffu, r1s, 2);
                if (tq == 0) {
                    atomicAdd(&g_qprobe[bh * 64 + i * 16 + gid], r0s);
                    atomicAdd(&g_qprobe[bh * 64 + i * 16 + gid + 8], r1s);
                }
            }
        } else {
            // warp covers 64 consecutive pixels = exactly one h row
            int hrow = blockIdx.x * 2 + wn;
#pragma unroll
            for (int i = 0; i < 4; i++) {
                int d0 = i * 16 + gid;
                float r0s = 0.f, r1s = 0.f;
#pragma unroll
                for (int n = 0; n < 8; n++) {
                    float a0 = fabsf(acc[i][n][0]), a1 = fabsf(acc[i][n][1]);
                    float a2 = fabsf(acc[i][n][2]), a3 = fabsf(acc[i][n][3]);
                    r0s += a0 + a1; r1s += a2 + a3;
                    int w0 = n * 8 + 2 * tq;
                    atomicAdd(&g_colabs[bh * 4096 + d0 * 64 + w0],           a0);
                    atomicAdd(&g_colabs[bh * 4096 + d0 * 64 + w0 + 1],       a1);
                    atomicAdd(&g_colabs[bh * 4096 + (d0 + 8) * 64 + w0],     a2);
                    atomicAdd(&g_colabs[bh * 4096 + (d0 + 8) * 64 + w0 + 1], a3);
                }
                r0s += __shfl_xor_sync(0xffffffffu, r0s, 1);
                r0s += __shfl_xor_sync(0xffffffffu, r0s, 2);
                r1s += __shfl_xor_sync(0xffffffffu, r1s, 1);
                r1s += __shfl_xor_sync(0xffffffffu, r1s, 2);
                if (tq == 0) {
                    atomicAdd(&g_rowabs[bh * 4096 + d0 * 64 + hrow],       r0s);
                    atomicAdd(&g_rowabs[bh * 4096 + (d0 + 8) * 64 + hrow], r1s);
                }
            }
        }
    }

#pragma unroll
    for (int i = 0; i < 4; i++) {
        int r = m0 + wm * 64 + i * 16 + gid;
#pragma unroll
        for (int n = 0; n < 8; n++) {
            int c = n0 + wn * 64 + n * 8 + 2 * tq;
            *(float2*)(Cp + (size_t)r * HW + c)       = make_float2(acc[i][n][0], acc[i][n][1]);
            *(float2*)(Cp + (size_t)(r + 8) * HW + c) = make_float2(acc[i][n][2], acc[i][n][3]);
        }
    }
}

// ---------------- w_out GEMM fused with final LN + residual (4-stage) ------
#define WF_BS_ST 72
#define WF_AS_BYTES 65536                       // 4 stages x 1024 uint4
#define WF_BS_BYTES 18432                       // 4 stages x 16 x 72 floats
#define WF_SMEM_BYTES (WF_AS_BYTES + WF_BS_BYTES + 4 * 64 * 4)

__global__ void __launch_bounds__(256)
wout_final_kernel(const float* __restrict__ qsrc,
                  const float* __restrict__ gw,
                  const float* __restrict__ bw,
                  const float* __restrict__ gamma,
                  float* __restrict__ outp) {
    extern __shared__ char dsm[];
    uint4* As4 = (uint4*)dsm;                          // [4][1024]
    float* Bs  = (float*)(dsm + WF_AS_BYTES);          // [4][16][72]
    float* cs    = (float*)(dsm + WF_AS_BYTES + WF_BS_BYTES);
    float* cs2   = cs + 64;
    float* cmean = cs2 + 64;
    float* cinv  = cmean + 64;

    const uint4* Ap4 = (const uint4*)g_woutp;          // [mtile2][kt32][512]
    const float* Bp = g_att + (size_t)blockIdx.z * 512 * HW;
    int n0 = blockIdx.x * 64;
    int tid = threadIdx.x, lane = tid & 31;
    int wid = tid >> 5;
    int wm = wid >> 1, wn = wid & 1;                   // 4x2
    int gid = lane >> 2, tq = lane & 3;

    int bk = tid >> 4;            // 0..15
    int bn = (tid & 15) * 4;      // 0..60

    auto load_stage = [&](int s, int kt) {
#pragma unroll
        for (int r = 0; r < 4; r++) {
            int idx = r * 256 + tid;
            int mt = idx >> 9, sub = idx & 511;
            uint32_t adst = (uint32_t)__cvta_generic_to_shared(&As4[s * 1024 + idx]);
            cpasync16(adst, Ap4 + (size_t)mt * (32 * 512) + kt * 512 + sub);
        }
        uint32_t bdst = (uint32_t)__cvta_generic_to_shared(&Bs[(s * 16 + bk) * WF_BS_ST + bn]);
        cpasync16(bdst, Bp + (size_t)(kt * 16 + bk) * HW + n0 + bn);
    };

    float acc[4][4][4];
#pragma unroll
    for (int i = 0; i < 4; i++)
#pragma unroll
        for (int j = 0; j < 4; j++)
#pragma unroll
            for (int r = 0; r < 4; r++) acc[i][j][r] = 0.f;

    load_stage(0, 0); CP_COMMIT();
    load_stage(1, 1); CP_COMMIT();
    load_stage(2, 2); CP_COMMIT();

    int mt = wm >> 1, mbb = (wm & 1) * 4;
    for (int kt = 0; kt < 32; kt++) {
        CP_WAIT2();
        __syncthreads();
        if (kt + 3 < 32) load_stage((kt + 3) & 3, kt + 3);
        CP_COMMIT();
        int s = kt & 3;

#pragma unroll
        for (int ks = 0; ks < 2; ks++) {
            int kk = ks * 8 + tq;
            uint4 af[4];
            uint32_t bf[4][2];
#pragma unroll
            for (int i = 0; i < 4; i++)
                af[i] = As4[s * 1024 + mt * 512 + (mbb + i) * 64 + ks * 32 + lane];
#pragma unroll
            for (int j = 0; j < 4; j++) {
                int c = wn * 32 + j * 8 + gid;
                bf[j][0] = __float_as_uint(Bs[(s * 16 + kk) * WF_BS_ST + c]);
                bf[j][1] = __float_as_uint(Bs[(s * 16 + kk + 4) * WF_BS_ST + c]);
            }
#pragma unroll
            for (int i = 0; i < 4; i++)
#pragma unroll
                for (int j = 0; j < 4; j++) {
                    asm volatile(
                        "mma.sync.aligned.m16n8k8.row.col.f32.tf32.tf32.f32 "
                        "{%0,%1,%2,%3}, {%4,%5,%6,%7}, {%8,%9}, {%0,%1,%2,%3};"
                        : "+f"(acc[i][j][0]), "+f"(acc[i][j][1]),
                          "+f"(acc[i][j][2]), "+f"(acc[i][j][3])
                        : "r"(af[i].x), "r"(af[i].y), "r"(af[i].z), "r"(af[i].w),
                          "r"(bf[j][0]), "r"(bf[j][1]));
                }
        }
    }

    // ---- per-pixel LN stats over all 256 channels ----
    if (tid < 64) { cs[tid] = 0.f; cs2[tid] = 0.f; }
    __syncthreads();
#pragma unroll
    for (int j = 0; j < 4; j++) {
        float s0 = 0.f, q0 = 0.f, s1 = 0.f, q1 = 0.f;
#pragma unroll
        for (int i = 0; i < 4; i++) {
            float a = acc[i][j][0], b2 = acc[i][j][2];
            s0 += a + b2; q0 += a * a + b2 * b2;
            float c1 = acc[i][j][1], d1 = acc[i][j][3];
            s1 += c1 + d1; q1 += c1 * c1 + d1 * d1;
        }
        s0 += __shfl_xor_sync(0xffffffffu, s0, 4);
        s0 += __shfl_xor_sync(0xffffffffu, s0, 8);
        s0 += __shfl_xor_sync(0xffffffffu, s0, 16);
        q0 += __shfl_xor_sync(0xffffffffu, q0, 4);
        q0 += __shfl_xor_sync(0xffffffffu, q0, 8);
        q0 += __shfl_xor_sync(0xffffffffu, q0, 16);
        s1 += __shfl_xor_sync(0xffffffffu, s1, 4);
        s1 += __shfl_xor_sync(0xffffffffu, s1, 8);
        s1 += __shfl_xor_sync(0xffffffffu, s1, 16);
        q1 += __shfl_xor_sync(0xffffffffu, q1, 4);
        q1 += __shfl_xor_sync(0xffffffffu, q1, 8);
        q1 += __shfl_xor_sync(0xffffffffu, q1, 16);
        if (gid == 0) {
            int c0 = wn * 32 + j * 8 + 2 * tq;
            atomicAdd(&cs[c0], s0);  atomicAdd(&cs2[c0], q0);
            atomicAdd(&cs[c0 + 1], s1); atomicAdd(&cs2[c0 + 1], q1);
        }
    }
    __syncthreads();
    if (tid < 64) {
        float mean = cs[tid] * (1.0f / CDIM);
        float var  = cs2[tid] * (1.0f / CDIM) - mean * mean;
        cmean[tid] = mean;
        cinv[tid]  = rsqrtf(var + 1e-5f);
    }
    __syncthreads();

    float gm = gamma[0];
    size_t obase = (size_t)blockIdx.z * CDIM * HW;
#pragma unroll
    for (int i = 0; i < 4; i++) {
        int r = wm * 64 + i * 16 + gid;
        float g0 = gw[r], b0 = bw[r];
        float g1 = gw[r + 8], b1 = bw[r + 8];
#pragma unroll
        for (int j = 0; j < 4; j++) {
            int c = wn * 32 + j * 8 + 2 * tq;
            int cg = n0 + c;
            float m0c = cmean[c], i0c = cinv[c];
            float m1c = cmean[c + 1], i1c = cinv[c + 1];
            float2 q0 = *(const float2*)(qsrc + obase + (size_t)r * HW + cg);
            float2 q1 = *(const float2*)(qsrc + obase + (size_t)(r + 8) * HW + cg);
            float2 o0, o1;
            o0.x = gm * ((acc[i][j][0] - m0c) * i0c * g0 + b0) + q0.x;
            o0.y = gm * ((acc[i][j][1] - m1c) * i1c * g0 + b0) + q0.y;
            o1.x = gm * ((acc[i][j][2] - m0c) * i0c * g1 + b1) + q1.x;
            o1.y = gm * ((acc[i][j][3] - m1c) * i1c * g1 + b1) + q1.y;
            *(float2*)(outp + obase + (size_t)r * HW + cg)       = o0;
            *(float2*)(outp + obase + (size_t)(r + 8) * HW + cg) = o1;
        }
    }
}

// ---------------- scores + top-8 selection ---------------------------------
__global__ void score_kernel() {
    int bh = blockIdx.x;
    int t = threadIdx.x;
    __shared__ float qp[64], sc[64];
    qp[t] = g_qprobe[bh * 64 + t];
    __syncthreads();

    float s = 0.f;
    for (int d = 0; d < 64; d++) s += qp[d] * g_rowabs[bh * 4096 + d * 64 + t];
    sc[t] = s;
    __syncthreads();
    if (t == 0) {
        for (int it = 0; it < 8; it++) {
            int best = 0; float bv = sc[0];
            for (int h = 1; h < 64; h++) if (sc[h] > bv) { bv = sc[h]; best = h; }
            g_idxh[bh * 8 + it] = best; sc[best] = -3e38f;
        }
    }
    __syncthreads();

    float s2 = 0.f;
    for (int d = 0; d < 64; d++) s2 += qp[d] * g_colabs[bh * 4096 + d * 64 + t];
    sc[t] = s2;
    __syncthreads();
    if (t == 0) {
        for (int it = 0; it < 8; it++) {
            int best = 0; float bv = sc[0];
            for (int w = 1; w < 64; w++) if (sc[w] > bv) { bv = sc[w]; best = w; }
            g_idxw[bh * 8 + it] = best; sc[best] = -3e38f;
        }
    }
}

// ---------------- gather selected K^T [d][j] and V [j][d] -------------------
__global__ void gather_kernel() {
    int bh = blockIdx.x;
    int b = bh >> 3, head = bh & 7;
    size_t kc = (size_t)(b * 16 + head) * 64 * HW;
    size_t vc = (size_t)(b * 16 + 8 + head) * 64 * HW;
    __shared__ int ih[8], iw[8];
    if (threadIdx.x < 8) ih[threadIdx.x] = g_idxh[bh * 8 + threadIdx.x];
    else if (threadIdx.x < 16) iw[threadIdx.x - 8] = g_idxw[bh * 8 + threadIdx.x - 8];
    __syncthreads();
    for (int t = threadIdx.x; t < 4096; t += 256) {
        int j = t >> 6, d = t & 63;
        int pix = ih[j >> 3] * 64 + iw[j & 7];
        g_kselT[bh * 4096 + d * 64 + j] = g_kv[kc + (size_t)d * HW + pix];
        g_vsel [bh * 4096 + t]          = g_kv[vc + (size_t)d * HW + pix];
    }
}

// ---------------- tensor-core attention ------------------------------------
#define KT_ST 72
#define QS_ST 136
#define PS_ST 68
#define ATTN_SMEM_FLOATS (4608 + 4608 + 8704)

__global__ void __launch_bounds__(128)
attn_mma_kernel() {
    extern __shared__ float sm[];
    float* kst = sm;                  // [d][j]
    float* vs  = sm + 4608;           // [j][d]
    float* qps = sm + 9216;           // qs [d][pix] then ps [pix][j]

    int bh = blockIdx.y;
    int pix0 = blockIdx.x * 128;
    int tid = threadIdx.x, lane = tid & 31, w = tid >> 5;
    int gid = lane >> 2, tq = lane & 3;
    int m0w = w * 32;
    size_t qb = (size_t)bh * 64 * HW + pix0;

    for (int t = tid; t < 4096; t += 128) {
        int r = t >> 6, c = t & 63;
        kst[r * KT_ST + c] = tf32r(g_kselT[bh * 4096 + t]);
        vs [r * KT_ST + c] = tf32r(g_vsel [bh * 4096 + t]);
    }
    for (int r = 0; r < 64; r += 2) {
        int rr = r + (tid >> 6);
        int cc = tid & 63;
        qps[rr * QS_ST + cc]      = tf32r(g_q[qb + (size_t)rr * HW + cc]);
        qps[rr * QS_ST + cc + 64] = tf32r(g_q[qb + (size_t)rr * HW + cc + 64]);
    }
    __syncthreads();

    float accs[2][8][4];
#pragma unroll
    for (int i = 0; i < 2; i++)
#pragma unroll
        for (int n = 0; n < 8; n++)
#pragma unroll
            for (int r = 0; r < 4; r++) accs[i][n][r] = 0.f;

#pragma unroll
    for (int k = 0; k < 8; k++) {
        int kk = k * 8;
        uint32_t a[2][4], b[8][2];
#pragma unroll
        for (int i = 0; i < 2; i++) {
            int mc = m0w + i * 16 + gid;
            a[i][0] = __float_as_uint(qps[(kk + tq) * QS_ST + mc]);
            a[i][1] = __float_as_uint(qps[(kk + tq) * QS_ST + mc + 8]);
            a[i][2] = __float_as_uint(qps[(kk + tq + 4) * QS_ST + mc]);
            a[i][3] = __float_as_uint(qps[(kk + tq + 4) * QS_ST + mc + 8]);
        }
#pragma unroll
        for (int n = 0; n < 8; n++) {
            b[n][0] = __float_as_uint(kst[(kk + tq) * KT_ST + n * 8 + gid]);
            b[n][1] = __float_as_uint(kst[(kk + tq + 4) * KT_ST + n * 8 + gid]);
        }
#pragma unroll
        for (int i = 0; i < 2; i++)
#pragma unroll
            for (int n = 0; n < 8; n++)
                asm volatile(
                    "mma.sync.aligned.m16n8k8.row.col.f32.tf32.tf32.f32 "
                    "{%0,%1,%2,%3}, {%4,%5,%6,%7}, {%8,%9}, {%0,%1,%2,%3};"
                    : "+f"(accs[i][n][0]), "+f"(accs[i][n][1]),
                      "+f"(accs[i][n][2]), "+f"(accs[i][n][3])
                    : "r"(a[i][0]), "r"(a[i][1]), "r"(a[i][2]), "r"(a[i][3]),
                      "r"(b[n][0]), "r"(b[n][1]));
    }

    float inv0[2], inv1[2];
#pragma unroll
    for (int i = 0; i < 2; i++) {
        float mx0 = -3e38f, mx1 = -3e38f;
#pragma unroll
        for (int n = 0; n < 8; n++) {
            mx0 = fmaxf(mx0, fmaxf(accs[i][n][0], accs[i][n][1]));
            mx1 = fmaxf(mx1, fmaxf(accs[i][n][2], accs[i][n][3]));
        }
        mx0 = fmaxf(mx0, __shfl_xor_sync(0xffffffffu, mx0, 1));
        mx0 = fmaxf(mx0, __shfl_xor_sync(0xffffffffu, mx0, 2));
        mx1 = fmaxf(mx1, __shfl_xor_sync(0xffffffffu, mx1, 1));
        mx1 = fmaxf(mx1, __shfl_xor_sync(0xffffffffu, mx1, 2));
        float s0 = 0.f, s1 = 0.f;
#pragma unroll
        for (int n = 0; n < 8; n++) {
            accs[i][n][0] = __expf(accs[i][n][0] - mx0);
            accs[i][n][1] = __expf(accs[i][n][1] - mx0);
            accs[i][n][2] = __expf(accs[i][n][2] - mx1);
            accs[i][n][3] = __expf(accs[i][n][3] - mx1);
            s0 += accs[i][n][0] + accs[i][n][1];
            s1 += accs[i][n][2] + accs[i][n][3];
        }
        s0 += __shfl_xor_sync(0xffffffffu, s0, 1);
        s0 += __shfl_xor_sync(0xffffffffu, s0, 2);
        s1 += __shfl_xor_sync(0xffffffffu, s1, 1);
        s1 += __shfl_xor_sync(0xffffffffu, s1, 2);
        inv0[i] = 1.0f / s0;
        inv1[i] = 1.0f / s1;
    }

    __syncthreads();
    float* ps = qps;
#pragma unroll
    for (int i = 0; i < 2; i++) {
        int r0 = m0w + i * 16 + gid;
#pragma unroll
        for (int n = 0; n < 8; n++) {
            int c = n * 8 + 2 * tq;
            ps[r0 * PS_ST + c]           = tf32r(accs[i][n][0]);
            ps[r0 * PS_ST + c + 1]       = tf32r(accs[i][n][1]);
            ps[(r0 + 8) * PS_ST + c]     = tf32r(accs[i][n][2]);
            ps[(r0 + 8) * PS_ST + c + 1] = tf32r(accs[i][n][3]);
        }
    }

    float acco[2][8][4];
#pragma unroll
    for (int i = 0; i < 2; i++)
#pragma unroll
        for (int n = 0; n < 8; n++)
#pragma unroll
            for (int r = 0; r < 4; r++) acco[i][n][r] = 0.f;

#pragma unroll
    for (int k = 0; k < 8; k++) {
        int kk = k * 8;
        uint32_t a[2][4], b[8][2];
#pragma unroll
        for (int i = 0; i < 2; i++) {
            int r0 = m0w + i * 16 + gid;
            a[i][0] = __float_as_uint(ps[r0 * PS_ST + kk + tq]);
            a[i][1] = __float_as_uint(ps[(r0 + 8) * PS_ST + kk + tq]);
            a[i][2] = __float_as_uint(ps[r0 * PS_ST + kk + tq + 4]);
            a[i][3] = __float_as_uint(ps[(r0 + 8) * PS_ST + kk + tq + 4]);
        }
#pragma unroll
        for (int n = 0; n < 8; n++) {
            b[n][0] = __float_as_uint(vs[(kk + tq) * KT_ST + n * 8 + gid]);
            b[n][1] = __float_as_uint(vs[(kk + tq + 4) * KT_ST + n * 8 + gid]);
        }
#pragma unroll
        for (int i = 0; i < 2; i++)
#pragma unroll
            for (int n = 0; n < 8; n++)
                asm volatile(
                    "mma.sync.aligned.m16n8k8.row.col.f32.tf32.tf32.f32 "
                    "{%0,%1,%2,%3}, {%4,%5,%6,%7}, {%8,%9}, {%0,%1,%2,%3};"
                    : "+f"(acco[i][n][0]), "+f"(acco[i][n][1]),
                      "+f"(acco[i][n][2]), "+f"(acco[i][n][3])
                    : "r"(a[i][0]), "r"(a[i][1]), "r"(a[i][2]), "r"(a[i][3]),
                      "r"(b[n][0]), "r"(b[n][1]));
    }

    size_t ob = (size_t)bh * 64 * HW + pix0;
#pragma unroll
    for (int i = 0; i < 2; i++) {
        int prow = m0w + i * 16 + gid;
#pragma unroll
        for (int n = 0; n < 8; n++) {
            int d0 = n * 8 + 2 * tq;
            g_att[ob + (size_t)d0 * HW + prow]           = tf32r(acco[i][n][0] * inv0[i]);
            g_att[ob + (size_t)(d0 + 1) * HW + prow]     = tf32r(acco[i][n][1] * inv0[i]);
            g_att[ob + (size_t)d0 * HW + prow + 8]       = tf32r(acco[i][n][2] * inv1[i]);
            g_att[ob + (size_t)(d0 + 1) * HW + prow + 8] = tf32r(acco[i][n][3] * inv1[i]);
        }
    }
}

// ---------------- launch ----------------------------------------------------
extern "C" void kernel_launch(void* const* d_in, const int* in_sizes, int n_in,
                              void* d_out, int out_size) {
    const float* query_source = (const float*)d_in[0];
    const float* context      = (const float*)d_in[1];
    const float* cn_g = (const float*)d_in[2];
    const float* cn_b = (const float*)d_in[3];
    const float* qn_g = (const float*)d_in[4];
    const float* qn_b = (const float*)d_in[5];
    const float* on_g = (const float*)d_in[6];
    const float* on_b = (const float*)d_in[7];
    const float* w_kv  = (const float*)d_in[8];
    const float* w_q   = (const float*)d_in[9];
    const float* w_out = (const float*)d_in[10];
    const float* gamma = (const float*)d_in[11];
    float* out = (float*)d_out;

    dim3 lnb(32, 8);
    const int attn_smem = ATTN_SMEM_FLOATS * 4;   // 71680 B
    cudaFuncSetAttribute(attn_mma_kernel,
                         cudaFuncAttributeMaxDynamicSharedMemorySize, attn_smem);
    cudaFuncSetAttribute(wout_final_kernel,
                         cudaFuncAttributeMaxDynamicSharedMemorySize, WF_SMEM_BYTES);

    zero_kernel<<<1024, 256>>>();
    prep_w<<<512, 256>>>(w_kv, w_q, w_out);
    ln_kernel<<<1024, lnb>>>(context, cn_g, cn_b, 0);
    ln_kernel<<<1024, lnb>>>(query_source, qn_g, qn_b, 1);

    tgemm_kernel<<<dim3(32, 12, 8), 128>>>(256, 3);   // fused kv + q

    score_kernel<<<64, 64>>>();
    gather_kernel<<<64, 256>>>();

    attn_mma_kernel<<<dim3(32, 64), 128, attn_smem>>>();

    wout_final_kernel<<<dim3(64, 1, 8), 256, WF_SMEM_BYTES>>>(
        query_source, on_g, on_b, gamma, out);
}

// round 14
// speedup vs baseline: 1.0380x; 1.0380x over previous
#include <cuda_runtime.h>
#include <math.h>
#include <stdint.h>

#define HW    4096
#define CDIM  256
#define BATCH 8
#define NBH   64     // B*HEADS
#define DH    64     // DIM_HEAD

// ---------------- scratch (device globals; no runtime allocation) ----------
__device__ float g_ctx[BATCH * CDIM * HW];        // layernormed context (tf32-rounded)
__device__ float g_qs [BATCH * CDIM * HW];        // layernormed query_source (tf32-rounded)
__device__ float g_q  [BATCH * 512  * HW];        // w_q output (l2-normalized)
__device__ float g_att[BATCH * 512  * HW];        // attention output (tf32-rounded)
__device__ float g_qprobe[NBH * DH];
__device__ float g_rowabs[NBH * DH * 64];         // [bh][d][h]
__device__ float g_colabs[NBH * DH * 64];         // [bh][d][w]
__device__ int   g_idxh[NBH * 8];
__device__ int   g_idxw[NBH * 8];
__device__ float g_kselT[NBH * 64 * DH];          // [bh][d][j]  (K^T for mma)
__device__ float g_vsel [NBH * 64 * DH];          // [bh][j][d]

// tf32-pre-rounded weights, packed in mma-fragment order:
// [mtile128][kt16][mblk16][ks8][lane32] -> float4 {A[m][k],A[m+8][k],A[m][k+4],A[m+8][k+4]}
__device__ float g_wkvp[512 * 256];               // K half only
__device__ float g_wqp [512 * 256];
__device__ float g_woutp[256 * 512];

__device__ __forceinline__ float tf32r(float x) {
    uint32_t u;
    asm("cvt.rna.tf32.f32 %0, %1;" : "=r"(u) : "f"(x));
    return __uint_as_float(u);
}

// ---------------- zero scratch reductions ----------------------------------
__global__ void zero_kernel() {
    int i = blockIdx.x * 256 + threadIdx.x;
    if (i < NBH * DH) g_qprobe[i] = 0.f;
    if (i < NBH * DH * 64) { g_rowabs[i] = 0.f; g_colabs[i] = 0.f; }
}

// ---------------- weight prep: tf32-round + pack into fragment order -------
// 384 blocks x 256 threads (K half of wkv, wq, wout).
__global__ void prep_w(const float* __restrict__ wkv,
                       const float* __restrict__ wq,
                       const float* __restrict__ wout) {
    int fid = blockIdx.x * 256 + threadIdx.x;
    const float* W; float4* Dst; int K, rel;
    if (fid < 32768)      { W = wkv;  Dst = (float4*)g_wkvp;  K = 256; rel = fid; }
    else if (fid < 65536) { W = wq;   Dst = (float4*)g_wqp;   K = 256; rel = fid - 32768; }
    else                  { W = wout; Dst = (float4*)g_woutp; K = 512; rel = fid - 65536; }
    int KT = K >> 4;
    int per_mtile = KT * 512;
    int mtile = rel / per_mtile;
    int r2 = rel - mtile * per_mtile;
    int kt = r2 >> 9;
    int sub = r2 & 511;
    int mblk = (sub >> 6) & 7;
    int ks = (sub >> 5) & 1;
    int lane = sub & 31;
    int gid = lane >> 2, tq = lane & 3;
    int m = mtile * 128 + mblk * 16 + gid;
    int k = kt * 16 + ks * 8 + tq;
    float4 v;
    v.x = tf32r(W[(size_t)m * K + k]);
    v.y = tf32r(W[(size_t)(m + 8) * K + k]);
    v.z = tf32r(W[(size_t)m * K + k + 4]);
    v.w = tf32r(W[(size_t)(m + 8) * K + k + 4]);
    Dst[rel] = v;
}

// ---------------- channel layernorm, both tensors in one launch ------------
// grid 2048: blocks [0,1024) -> ctx, [1024,2048) -> qs. Per-pixel numerics
// bit-identical to the round-6 scalar kernel.
__global__ void ln_kernel(const float* __restrict__ xc,
                          const float* __restrict__ xq,
                          const float* __restrict__ cg, const float* __restrict__ cb,
                          const float* __restrict__ qg, const float* __restrict__ qb) {
    int sel = blockIdx.x >> 10;
    const float* x  = sel ? xq : xc;
    const float* gw = sel ? qg : cg;
    const float* bw = sel ? qb : cb;
    float* out = sel ? g_qs : g_ctx;
    int tx = threadIdx.x, ty = threadIdx.y;
    int gp = (blockIdx.x & 1023) * 32 + tx;
    int bidx = gp >> 12;
    int p = gp & (HW - 1);
    size_t base = (size_t)bidx * CDIM * HW + p;

    float vals[32];
    float s = 0.f, s2 = 0.f;
#pragma unroll
    for (int i = 0; i < 32; i++) {
        int c = ty + i * 8;
        float v = x[base + (size_t)c * HW];
        vals[i] = v; s += v; s2 += v * v;
    }
    __shared__ float rs[8][32], rs2[8][32];
    rs[ty][tx] = s; rs2[ty][tx] = s2;
    __syncthreads();
    for (int st = 4; st > 0; st >>= 1) {
        if (ty < st) { rs[ty][tx] += rs[ty + st][tx]; rs2[ty][tx] += rs2[ty + st][tx]; }
        __syncthreads();
    }
    float mean = rs[0][tx] * (1.0f / CDIM);
    float var  = rs2[0][tx] * (1.0f / CDIM) - mean * mean;
    float inv  = rsqrtf(var + 1e-5f);
#pragma unroll
    for (int i = 0; i < 32; i++) {
        int c = ty + i * 8;
        out[base + (size_t)c * HW] = tf32r((vals[i] - mean) * inv * gw[c] + bw[c]);
    }
}

// ---------------- cp.async helpers -----------------------------------------
__device__ __forceinline__ void cpasync16(uint32_t smem, const void* g) {
    asm volatile("cp.async.cg.shared.global [%0], [%1], 16;\n" :: "r"(smem), "l"(g));
}
#define CP_COMMIT() asm volatile("cp.async.commit_group;\n" ::: "memory")
#define CP_WAIT2()  asm volatile("cp.async.wait_group 2;\n" ::: "memory")

// ---------------- tensor-core GEMM: K-stats (no store) + q -----------------
// grid (32, 8, 8): y<4 -> K stats tile y (NO output store), y>=4 -> q tile.
// 128 threads / 4 warps (2x2), 64x64 warp tiles, 4-stage pipeline.
#define BS_STRIDE 136

__global__ void __launch_bounds__(128)
tgemm_kernel() {
    int by = blockIdx.y;
    int selEff;
    if (by < 4) selEff = 0;
    else { selEff = 1; by -= 4; }
    const uint4* Ap4; const float* Bp; float* Cp;
    if (selEff == 0) { Ap4 = (const uint4*)g_wkvp; Bp = g_ctx; Cp = nullptr; }
    else             { Ap4 = (const uint4*)g_wqp;  Bp = g_qs;  Cp = g_q;   }
    const int K = 256, KT = 16;
    Bp += (size_t)blockIdx.z * K * HW;
    if (Cp) Cp += (size_t)blockIdx.z * 512 * HW;
    Ap4 += (size_t)by * (KT * 512);

    __shared__ __align__(16) uint4 As4[4][512];
    __shared__ __align__(16) float Bs[4][16][BS_STRIDE];

    int m0 = by * 128, n0 = blockIdx.x * 128;
    int tid = threadIdx.x;
    int wid = tid >> 5, lane = tid & 31;
    int wm = wid >> 1, wn = wid & 1;          // warp 2x2, 64x64 tiles
    int gid = lane >> 2, tq = lane & 3;

    int bk = tid >> 3;            // 0..15
    int bn = (tid & 7) * 16;      // 0..112

    auto load_stage = [&](int s, int kt) {
#pragma unroll
        for (int r = 0; r < 4; r++) {
            uint32_t adst = (uint32_t)__cvta_generic_to_shared(&As4[s][tid + r * 128]);
            cpasync16(adst, Ap4 + kt * 512 + tid + r * 128);
        }
        uint32_t bdst = (uint32_t)__cvta_generic_to_shared(&Bs[s][bk][bn]);
        const float* bsrc = Bp + (size_t)(kt * 16 + bk) * HW + n0 + bn;
#pragma unroll
        for (int r = 0; r < 4; r++)
            cpasync16(bdst + r * 16, bsrc + r * 4);
    };

    float acc[4][8][4];
#pragma unroll
    for (int i = 0; i < 4; i++)
#pragma unroll
        for (int n = 0; n < 8; n++)
#pragma unroll
            for (int r = 0; r < 4; r++) acc[i][n][r] = 0.f;

    load_stage(0, 0); CP_COMMIT();
    load_stage(1, 1); CP_COMMIT();
    load_stage(2, 2); CP_COMMIT();

    for (int kt = 0; kt < KT; kt++) {
        CP_WAIT2();
        __syncthreads();
        if (kt + 3 < KT) load_stage((kt + 3) & 3, kt + 3);
        CP_COMMIT();
        int s = kt & 3;

#pragma unroll
        for (int ks = 0; ks < 2; ks++) {
            int kk = ks * 8 + tq;
            uint4 af[4];
            uint32_t bf[8][2];
#pragma unroll
            for (int i = 0; i < 4; i++)
                af[i] = As4[s][(4 * wm + i) * 64 + ks * 32 + lane];
#pragma unroll
            for (int n = 0; n < 8; n++) {
                int c = wn * 64 + n * 8 + gid;
                bf[n][0] = __float_as_uint(Bs[s][kk][c]);
                bf[n][1] = __float_as_uint(Bs[s][kk + 4][c]);
            }
#pragma unroll
            for (int i = 0; i < 4; i++)
#pragma unroll
                for (int n = 0; n < 8; n++) {
                    asm volatile(
                        "mma.sync.aligned.m16n8k8.row.col.f32.tf32.tf32.f32 "
                        "{%0,%1,%2,%3}, {%4,%5,%6,%7}, {%8,%9}, {%0,%1,%2,%3};"
                        : "+f"(acc[i][n][0]), "+f"(acc[i][n][1]),
                          "+f"(acc[i][n][2]), "+f"(acc[i][n][3])
                        : "r"(af[i].x), "r"(af[i].y), "r"(af[i].z), "r"(af[i].w),
                          "r"(bf[n][0]), "r"(bf[n][1]));
                }
        }
    }

    // l2-normalize over d per pixel column (warp holds all 64 d of its head)
    float inv_c[8][2];
#pragma unroll
    for (int n = 0; n < 8; n++) {
        float s0 = 0.f, s1 = 0.f;
#pragma unroll
        for (int i = 0; i < 4; i++) {
            s0 += acc[i][n][0] * acc[i][n][0] + acc[i][n][2] * acc[i][n][2];
            s1 += acc[i][n][1] * acc[i][n][1] + acc[i][n][3] * acc[i][n][3];
        }
        s0 += __shfl_xor_sync(0xffffffffu, s0, 4);
        s0 += __shfl_xor_sync(0xffffffffu, s0, 8);
        s0 += __shfl_xor_sync(0xffffffffu, s0, 16);
        s1 += __shfl_xor_sync(0xffffffffu, s1, 4);
        s1 += __shfl_xor_sync(0xffffffffu, s1, 8);
        s1 += __shfl_xor_sync(0xffffffffu, s1, 16);
        inv_c[n][0] = 1.0f / fmaxf(sqrtf(s0), 1e-12f);
        inv_c[n][1] = 1.0f / fmaxf(sqrtf(s1), 1e-12f);
    }
#pragma unroll
    for (int i = 0; i < 4; i++)
#pragma unroll
        for (int n = 0; n < 8; n++) {
            acc[i][n][0] *= inv_c[n][0];
            acc[i][n][1] *= inv_c[n][1];
            acc[i][n][2] *= inv_c[n][0];
            acc[i][n][3] *= inv_c[n][1];
        }

    int head = by * 2 + wm;
    int bh = blockIdx.z * 8 + head;

    if (selEff == 1) {
        // qprobe + store normalized q
#pragma unroll
        for (int i = 0; i < 4; i++) {
            float r0s = 0.f, r1s = 0.f;
#pragma unroll
            for (int n = 0; n < 8; n++) {
                r0s += acc[i][n][0] + acc[i][n][1];
                r1s += acc[i][n][2] + acc[i][n][3];
            }
            r0s += __shfl_xor_sync(0xffffffffu, r0s, 1);
            r0s += __shfl_xor_sync(0xffffffffu, r0s, 2);
            r1s += __shfl_xor_sync(0xffffffffu, r1s, 1);
            r1s += __shfl_xor_sync(0xffffffffu, r1s, 2);
            if (tq == 0) {
                atomicAdd(&g_qprobe[bh * 64 + i * 16 + gid], r0s);
                atomicAdd(&g_qprobe[bh * 64 + i * 16 + gid + 8], r1s);
            }
        }
#pragma unroll
        for (int i = 0; i < 4; i++) {
            int r = m0 + wm * 64 + i * 16 + gid;
#pragma unroll
            for (int n = 0; n < 8; n++) {
                int c = n0 + wn * 64 + n * 8 + 2 * tq;
                *(float2*)(Cp + (size_t)r * HW + c)       = make_float2(acc[i][n][0], acc[i][n][1]);
                *(float2*)(Cp + (size_t)(r + 8) * HW + c) = make_float2(acc[i][n][2], acc[i][n][3]);
            }
        }
    } else {
        // K stats only: rowabs[bh][d][h], colabs[bh][d][w]. No store.
        int hrow = blockIdx.x * 2 + wn;
#pragma unroll
        for (int i = 0; i < 4; i++) {
            int d0 = i * 16 + gid;
            float r0s = 0.f, r1s = 0.f;
#pragma unroll
            for (int n = 0; n < 8; n++) {
                float a0 = fabsf(acc[i][n][0]), a1 = fabsf(acc[i][n][1]);
                float a2 = fabsf(acc[i][n][2]), a3 = fabsf(acc[i][n][3]);
                r0s += a0 + a1; r1s += a2 + a3;
                int w0 = n * 8 + 2 * tq;
                atomicAdd(&g_colabs[bh * 4096 + d0 * 64 + w0],           a0);
                atomicAdd(&g_colabs[bh * 4096 + d0 * 64 + w0 + 1],       a1);
                atomicAdd(&g_colabs[bh * 4096 + (d0 + 8) * 64 + w0],     a2);
                atomicAdd(&g_colabs[bh * 4096 + (d0 + 8) * 64 + w0 + 1], a3);
            }
            r0s += __shfl_xor_sync(0xffffffffu, r0s, 1);
            r0s += __shfl_xor_sync(0xffffffffu, r0s, 2);
            r1s += __shfl_xor_sync(0xffffffffu, r1s, 1);
            r1s += __shfl_xor_sync(0xffffffffu, r1s, 2);
            if (tq == 0) {
                atomicAdd(&g_rowabs[bh * 4096 + d0 * 64 + hrow],       r0s);
                atomicAdd(&g_rowabs[bh * 4096 + (d0 + 8) * 64 + hrow], r1s);
            }
        }
    }
}

// ---------------- scores + top-8 selection ---------------------------------
__global__ void score_kernel() {
    int bh = blockIdx.x;
    int t = threadIdx.x;
    __shared__ float qp[64], sc[64];
    qp[t] = g_qprobe[bh * 64 + t];
    __syncthreads();

    float s = 0.f;
    for (int d = 0; d < 64; d++) s += qp[d] * g_rowabs[bh * 4096 + d * 64 + t];
    sc[t] = s;
    __syncthreads();
    if (t == 0) {
        for (int it = 0; it < 8; it++) {
            int best = 0; float bv = sc[0];
            for (int h = 1; h < 64; h++) if (sc[h] > bv) { bv = sc[h]; best = h; }
            g_idxh[bh * 8 + it] = best; sc[best] = -3e38f;
        }
    }
    __syncthreads();

    float s2 = 0.f;
    for (int d = 0; d < 64; d++) s2 += qp[d] * g_colabs[bh * 4096 + d * 64 + t];
    sc[t] = s2;
    __syncthreads();
    if (t == 0) {
        for (int it = 0; it < 8; it++) {
            int best = 0; float bv = sc[0];
            for (int w = 1; w < 64; w++) if (sc[w] > bv) { bv = sc[w]; best = w; }
            g_idxw[bh * 8 + it] = best; sc[best] = -3e38f;
        }
    }
}

// ---------------- K/V at selected pixels (fp32, smem-staged) ---------------
// grid (64, 2): x=bh, y: 0=K (with l2norm), 1=V. 256 threads.
// csm[64][257] gathered ctx columns; wsm[256][68] head weights.
#define KV_C_ST 257
#define KV_W_ST 68
#define KVSEL_SMEM_BYTES ((64 * KV_C_ST + 256 * KV_W_ST) * 4)

__global__ void __launch_bounds__(256)
kvsel_kernel(const float* __restrict__ wkv) {
    extern __shared__ float ksm[];
    float* csm = ksm;                       // [j][c]
    float* wsm = ksm + 64 * KV_C_ST;        // [c][d]
    __shared__ int pix[64];

    int bh = blockIdx.x, isV = blockIdx.y;
    int b = bh >> 3, head = bh & 7;
    int t = threadIdx.x;
    if (t < 64) pix[t] = g_idxh[bh * 8 + (t >> 3)] * 64 + g_idxw[bh * 8 + (t & 7)];
    __syncthreads();

    // stage weights (raw fp32): rows isV*512 + head*64 + d
    const float* wv = wkv + (size_t)(isV * 512 + head * 64) * 256;
#pragma unroll 4
    for (int it = 0; it < 64; it++) {
        int idx = it * 256 + t;
        int d = idx >> 8, c = idx & 255;
        wsm[c * KV_W_ST + d] = wv[d * 256 + c];
    }
    // stage selected ctx columns
    const float* ctx = g_ctx + (size_t)b * CDIM * HW;
#pragma unroll 4
    for (int it = 0; it < 64; it++) {
        int idx = it * 256 + t;
        int j = idx >> 8, c = idx & 255;
        csm[j * KV_C_ST + c] = __ldg(ctx + (size_t)c * HW + pix[j]);
    }
    __syncthreads();

    int j = t >> 2, dq = t & 3;
    float acc[16];
#pragma unroll
    for (int i = 0; i < 16; i++) acc[i] = 0.f;
    const float* crow = csm + j * KV_C_ST;
#pragma unroll 4
    for (int c = 0; c < 256; c++) {
        float xv = crow[c];
        const float4* wr = (const float4*)(wsm + c * KV_W_ST + dq * 16);
        float4 w0 = wr[0], w1 = wr[1], w2 = wr[2], w3 = wr[3];
        acc[0]  += w0.x * xv; acc[1]  += w0.y * xv; acc[2]  += w0.z * xv; acc[3]  += w0.w * xv;
        acc[4]  += w1.x * xv; acc[5]  += w1.y * xv; acc[6]  += w1.z * xv; acc[7]  += w1.w * xv;
        acc[8]  += w2.x * xv; acc[9]  += w2.y * xv; acc[10] += w2.z * xv; acc[11] += w2.w * xv;
        acc[12] += w3.x * xv; acc[13] += w3.y * xv; acc[14] += w3.z * xv; acc[15] += w3.w * xv;
    }

    if (isV) {
#pragma unroll
        for (int i = 0; i < 16; i++)
            g_vsel[bh * 4096 + j * 64 + dq * 16 + i] = acc[i];
    } else {
        // l2 norm over all 64 d of this pixel (4 dq threads hold 16 each)
        float s = 0.f;
#pragma unroll
        for (int i = 0; i < 16; i++) s += acc[i] * acc[i];
        s += __shfl_xor_sync(0xffffffffu, s, 1);
        s += __shfl_xor_sync(0xffffffffu, s, 2);
        float inv = 1.0f / fmaxf(sqrtf(s), 1e-12f);
#pragma unroll
        for (int i = 0; i < 16; i++)
            g_kselT[bh * 4096 + (dq * 16 + i) * 64 + j] = acc[i] * inv;
    }
}

// ---------------- tensor-core attention ------------------------------------
#define KT_ST 72
#define QS_ST 136
#define PS_ST 68
#define ATTN_SMEM_FLOATS (4608 + 4608 + 8704)

__global__ void __launch_bounds__(128)
attn_mma_kernel() {
    extern __shared__ float sm[];
    float* kst = sm;
    float* vs  = sm + 4608;
    float* qps = sm + 9216;

    int bh = blockIdx.y;
    int pix0 = blockIdx.x * 128;
    int tid = threadIdx.x, lane = tid & 31, w = tid >> 5;
    int gid = lane >> 2, tq = lane & 3;
    int m0w = w * 32;
    size_t qb = (size_t)bh * 64 * HW + pix0;

    for (int t = tid; t < 4096; t += 128) {
        int r = t >> 6, c = t & 63;
        kst[r * KT_ST + c] = tf32r(g_kselT[bh * 4096 + t]);
        vs [r * KT_ST + c] = tf32r(g_vsel [bh * 4096 + t]);
    }
    for (int r = 0; r < 64; r += 2) {
        int rr = r + (tid >> 6);
        int cc = tid & 63;
        qps[rr * QS_ST + cc]      = tf32r(g_q[qb + (size_t)rr * HW + cc]);
        qps[rr * QS_ST + cc + 64] = tf32r(g_q[qb + (size_t)rr * HW + cc + 64]);
    }
    __syncthreads();

    float accs[2][8][4];
#pragma unroll
    for (int i = 0; i < 2; i++)
#pragma unroll
        for (int n = 0; n < 8; n++)
#pragma unroll
            for (int r = 0; r < 4; r++) accs[i][n][r] = 0.f;

#pragma unroll
    for (int k = 0; k < 8; k++) {
        int kk = k * 8;
        uint32_t a[2][4], b[8][2];
#pragma unroll
        for (int i = 0; i < 2; i++) {
            int mc = m0w + i * 16 + gid;
            a[i][0] = __float_as_uint(qps[(kk + tq) * QS_ST + mc]);
            a[i][1] = __float_as_uint(qps[(kk + tq) * QS_ST + mc + 8]);
            a[i][2] = __float_as_uint(qps[(kk + tq + 4) * QS_ST + mc]);
            a[i][3] = __float_as_uint(qps[(kk + tq + 4) * QS_ST + mc + 8]);
        }
#pragma unroll
        for (int n = 0; n < 8; n++) {
            b[n][0] = __float_as_uint(kst[(kk + tq) * KT_ST + n * 8 + gid]);
            b[n][1] = __float_as_uint(kst[(kk + tq + 4) * KT_ST + n * 8 + gid]);
        }
#pragma unroll
        for (int i = 0; i < 2; i++)
#pragma unroll
            for (int n = 0; n < 8; n++)
                asm volatile(
                    "mma.sync.aligned.m16n8k8.row.col.f32.tf32.tf32.f32 "
                    "{%0,%1,%2,%3}, {%4,%5,%6,%7}, {%8,%9}, {%0,%1,%2,%3};"
                    : "+f"(accs[i][n][0]), "+f"(accs[i][n][1]),
                      "+f"(accs[i][n][2]), "+f"(accs[i][n][3])
                    : "r"(a[i][0]), "r"(a[i][1]), "r"(a[i][2]), "r"(a[i][3]),
                      "r"(b[n][0]), "r"(b[n][1]));
    }

    float inv0[2], inv1[2];
#pragma unroll
    for (int i = 0; i < 2; i++) {
        float mx0 = -3e38f, mx1 = -3e38f;
#pragma unroll
        for (int n = 0; n < 8; n++) {
            mx0 = fmaxf(mx0, fmaxf(accs[i][n][0], accs[i][n][1]));
            mx1 = fmaxf(mx1, fmaxf(accs[i][n][2], accs[i][n][3]));
        }
        mx0 = fmaxf(mx0, __shfl_xor_sync(0xffffffffu, mx0, 1));
        mx0 = fmaxf(mx0, __shfl_xor_sync(0xffffffffu, mx0, 2));
        mx1 = fmaxf(mx1, __shfl_xor_sync(0xffffffffu, mx1, 1));
        mx1 = fmaxf(mx1, __shfl_xor_sync(0xffffffffu, mx1, 2));
        float s0 = 0.f, s1 = 0.f;
#pragma unroll
        for (int n = 0; n < 8; n++) {
            accs[i][n][0] = __expf(accs[i][n][0] - mx0);
            accs[i][n][1] = __expf(accs[i][n][1] - mx0);
            accs[i][n][2] = __expf(accs[i][n][2] - mx1);
            accs[i][n][3] = __expf(accs[i][n][3] - mx1);
            s0 += accs[i][n][0] + accs[i][n][1];
            s1 += accs[i][n][2] + accs[i][n][3];
        }
        s0 += __shfl_xor_sync(0xffffffffu, s0, 1);
        s0 += __shfl_xor_sync(0xffffffffu, s0, 2);
        s1 += __shfl_xor_sync(0xffffffffu, s1, 1);
        s1 += __shfl_xor_sync(0xffffffffu, s1, 2);
        inv0[i] = 1.0f / s0;
        inv1[i] = 1.0f / s1;
    }

    __syncthreads();
    float* ps = qps;
#pragma unroll
    for (int i = 0; i < 2; i++) {
        int r0 = m0w + i * 16 + gid;
#pragma unroll
        for (int n = 0; n < 8; n++) {
            int c = n * 8 + 2 * tq;
            ps[r0 * PS_ST + c]           = tf32r(accs[i][n][0]);
            ps[r0 * PS_ST + c + 1]       = tf32r(accs[i][n][1]);
            ps[(r0 + 8) * PS_ST + c]     = tf32r(accs[i][n][2]);
            ps[(r0 + 8) * PS_ST + c + 1] = tf32r(accs[i][n][3]);
        }
    }

    float acco[2][8][4];
#pragma unroll
    for (int i = 0; i < 2; i++)
#pragma unroll
        for (int n = 0; n < 8; n++)
#pragma unroll
            for (int r = 0; r < 4; r++) acco[i][n][r] = 0.f;

#pragma unroll
    for (int k = 0; k < 8; k++) {
        int kk = k * 8;
        uint32_t a[2][4], b[8][2];
#pragma unroll
        for (int i = 0; i < 2; i++) {
            int r0 = m0w + i * 16 + gid;
            a[i][0] = __float_as_uint(ps[r0 * PS_ST + kk + tq]);
            a[i][1] = __float_as_uint(ps[(r0 + 8) * PS_ST + kk + tq]);
            a[i][2] = __float_as_uint(ps[r0 * PS_ST + kk + tq + 4]);
            a[i][3] = __float_as_uint(ps[(r0 + 8) * PS_ST + kk + tq + 4]);
        }
#pragma unroll
        for (int n = 0; n < 8; n++) {
            b[n][0] = __float_as_uint(vs[(kk + tq) * KT_ST + n * 8 + gid]);
            b[n][1] = __float_as_uint(vs[(kk + tq + 4) * KT_ST + n * 8 + gid]);
        }
#pragma unroll
        for (int i = 0; i < 2; i++)
#pragma unroll
            for (int n = 0; n < 8; n++)
                asm volatile(
                    "mma.sync.aligned.m16n8k8.row.col.f32.tf32.tf32.f32 "
                    "{%0,%1,%2,%3}, {%4,%5,%6,%7}, {%8,%9}, {%0,%1,%2,%3};"
                    : "+f"(acco[i][n][0]), "+f"(acco[i][n][1]),
                      "+f"(acco[i][n][2]), "+f"(acco[i][n][3])
                    : "r"(a[i][0]), "r"(a[i][1]), "r"(a[i][2]), "r"(a[i][3]),
                      "r"(b[n][0]), "r"(b[n][1]));
    }

    size_t ob = (size_t)bh * 64 * HW + pix0;
#pragma unroll
    for (int i = 0; i < 2; i++) {
        int prow = m0w + i * 16 + gid;
#pragma unroll
        for (int n = 0; n < 8; n++) {
            int d0 = n * 8 + 2 * tq;
            g_att[ob + (size_t)d0 * HW + prow]           = tf32r(acco[i][n][0] * inv0[i]);
            g_att[ob + (size_t)(d0 + 1) * HW + prow]     = tf32r(acco[i][n][1] * inv0[i]);
            g_att[ob + (size_t)d0 * HW + prow + 8]       = tf32r(acco[i][n][2] * inv1[i]);
            g_att[ob + (size_t)(d0 + 1) * HW + prow + 8] = tf32r(acco[i][n][3] * inv1[i]);
        }
    }
}

// ---------------- w_out GEMM fused with final LN + residual (4-stage) ------
#define WF_BS_ST 72
#define WF_AS_BYTES 65536
#define WF_BS_BYTES 18432
#define WF_SMEM_BYTES (WF_AS_BYTES + WF_BS_BYTES + 4 * 64 * 4)

__global__ void __launch_bounds__(256)
wout_final_kernel(const float* __restrict__ qsrc,
                  const float* __restrict__ gw,
                  const float* __restrict__ bw,
                  const float* __restrict__ gamma,
                  float* __restrict__ outp) {
    extern __shared__ char dsm[];
    uint4* As4 = (uint4*)dsm;
    float* Bs  = (float*)(dsm + WF_AS_BYTES);
    float* cs    = (float*)(dsm + WF_AS_BYTES + WF_BS_BYTES);
    float* cs2   = cs + 64;
    float* cmean = cs2 + 64;
    float* cinv  = cmean + 64;

    const uint4* Ap4 = (const uint4*)g_woutp;
    const float* Bp = g_att + (size_t)blockIdx.z * 512 * HW;
    int n0 = blockIdx.x * 64;
    int tid = threadIdx.x, lane = tid & 31;
    int wid = tid >> 5;
    int wm = wid >> 1, wn = wid & 1;
    int gid = lane >> 2, tq = lane & 3;

    int bk = tid >> 4;
    int bn = (tid & 15) * 4;

    auto load_stage = [&](int s, int kt) {
#pragma unroll
        for (int r = 0; r < 4; r++) {
            int idx = r * 256 + tid;
            int mt = idx >> 9, sub = idx & 511;
            uint32_t adst = (uint32_t)__cvta_generic_to_shared(&As4[s * 1024 + idx]);
            cpasync16(adst, Ap4 + (size_t)mt * (32 * 512) + kt * 512 + sub);
        }
        uint32_t bdst = (uint32_t)__cvta_generic_to_shared(&Bs[(s * 16 + bk) * WF_BS_ST + bn]);
        cpasync16(bdst, Bp + (size_t)(kt * 16 + bk) * HW + n0 + bn);
    };

    float acc[4][4][4];
#pragma unroll
    for (int i = 0; i < 4; i++)
#pragma unroll
        for (int j = 0; j < 4; j++)
#pragma unroll
            for (int r = 0; r < 4; r++) acc[i][j][r] = 0.f;

    load_stage(0, 0); CP_COMMIT();
    load_stage(1, 1); CP_COMMIT();
    load_stage(2, 2); CP_COMMIT();

    int mt = wm >> 1, mbb = (wm & 1) * 4;
    for (int kt = 0; kt < 32; kt++) {
        CP_WAIT2();
        __syncthreads();
        if (kt + 3 < 32) load_stage((kt + 3) & 3, kt + 3);
        CP_COMMIT();
        int s = kt & 3;

#pragma unroll
        for (int ks = 0; ks < 2; ks++) {
            int kk = ks * 8 + tq;
            uint4 af[4];
            uint32_t bf[4][2];
#pragma unroll
            for (int i = 0; i < 4; i++)
                af[i] = As4[s * 1024 + mt * 512 + (mbb + i) * 64 + ks * 32 + lane];
#pragma unroll
            for (int j = 0; j < 4; j++) {
                int c = wn * 32 + j * 8 + gid;
                bf[j][0] = __float_as_uint(Bs[(s * 16 + kk) * WF_BS_ST + c]);
                bf[j][1] = __float_as_uint(Bs[(s * 16 + kk + 4) * WF_BS_ST + c]);
            }
#pragma unroll
            for (int i = 0; i < 4; i++)
#pragma unroll
                for (int j = 0; j < 4; j++) {
                    asm volatile(
                        "mma.sync.aligned.m16n8k8.row.col.f32.tf32.tf32.f32 "
                        "{%0,%1,%2,%3}, {%4,%5,%6,%7}, {%8,%9}, {%0,%1,%2,%3};"
                        : "+f"(acc[i][j][0]), "+f"(acc[i][j][1]),
                          "+f"(acc[i][j][2]), "+f"(acc[i][j][3])
                        : "r"(af[i].x), "r"(af[i].y), "r"(af[i].z), "r"(af[i].w),
                          "r"(bf[j][0]), "r"(bf[j][1]));
                }
        }
    }

    if (tid < 64) { cs[tid] = 0.f; cs2[tid] = 0.f; }
    __syncthreads();
#pragma unroll
    for (int j = 0; j < 4; j++) {
        float s0 = 0.f, q0 = 0.f, s1 = 0.f, q1 = 0.f;
#pragma unroll
        for (int i = 0; i < 4; i++) {
            float a = acc[i][j][0], b2 = acc[i][j][2];
            s0 += a + b2; q0 += a * a + b2 * b2;
            float c1 = acc[i][j][1], d1 = acc[i][j][3];
            s1 += c1 + d1; q1 += c1 * c1 + d1 * d1;
        }
        s0 += __shfl_xor_sync(0xffffffffu, s0, 4);
        s0 += __shfl_xor_sync(0xffffffffu, s0, 8);
        s0 += __shfl_xor_sync(0xffffffffu, s0, 16);
        q0 += __shfl_xor_sync(0xffffffffu, q0, 4);
        q0 += __shfl_xor_sync(0xffffffffu, q0, 8);
        q0 += __shfl_xor_sync(0xffffffffu, q0, 16);
        s1 += __shfl_xor_sync(0xffffffffu, s1, 1 * 4);
        s1 += __shfl_xor_sync(0xffffffffu, s1, 8);
        s1 += __shfl_xor_sync(0xffffffffu, s1, 16);
        q1 += __shfl_xor_sync(0xffffffffu, q1, 4);
        q1 += __shfl_xor_sync(0xffffffffu, q1, 8);
        q1 += __shfl_xor_sync(0xffffffffu, q1, 16);
        if (gid == 0) {
            int c0 = wn * 32 + j * 8 + 2 * tq;
            atomicAdd(&cs[c0], s0);  atomicAdd(&cs2[c0], q0);
            atomicAdd(&cs[c0 + 1], s1); atomicAdd(&cs2[c0 + 1], q1);
        }
    }
    __syncthreads();
    if (tid < 64) {
        float mean = cs[tid] * (1.0f / CDIM);
        float var  = cs2[tid] * (1.0f / CDIM) - mean * mean;
        cmean[tid] = mean;
        cinv[tid]  = rsqrtf(var + 1e-5f);
    }
    __syncthreads();

    float gm = gamma[0];
    size_t obase = (size_t)blockIdx.z * CDIM * HW;
#pragma unroll
    for (int i = 0; i < 4; i++) {
        int r = wm * 64 + i * 16 + gid;
        float g0 = gw[r], b0 = bw[r];
        float g1 = gw[r + 8], b1 = bw[r + 8];
#pragma unroll
        for (int j = 0; j < 4; j++) {
            int c = wn * 32 + j * 8 + 2 * tq;
            int cg = n0 + c;
            float m0c = cmean[c], i0c = cinv[c];
            float m1c = cmean[c + 1], i1c = cinv[c + 1];
            float2 q0 = *(const float2*)(qsrc + obase + (size_t)r * HW + cg);
            float2 q1 = *(const float2*)(qsrc + obase + (size_t)(r + 8) * HW + cg);
            float2 o0, o1;
            o0.x = gm * ((acc[i][j][0] - m0c) * i0c * g0 + b0) + q0.x;
            o0.y = gm * ((acc[i][j][1] - m1c) * i1c * g0 + b0) + q0.y;
            o1.x = gm * ((acc[i][j][2] - m0c) * i0c * g1 + b1) + q1.x;
            o1.y = gm * ((acc[i][j][3] - m1c) * i1c * g1 + b1) + q1.y;
            *(float2*)(outp + obase + (size_t)r * HW + cg)       = o0;
            *(float2*)(outp + obase + (size_t)(r + 8) * HW + cg) = o1;
        }
    }
}

// ---------------- launch ----------------------------------------------------
extern "C" void kernel_launch(void* const* d_in, const int* in_sizes, int n_in,
                              void* d_out, int out_size) {
    const float* query_source = (const float*)d_in[0];
    const float* context      = (const float*)d_in[1];
    const float* cn_g = (const float*)d_in[2];
    const float* cn_b = (const float*)d_in[3];
    const float* qn_g = (const float*)d_in[4];
    const float* qn_b = (const float*)d_in[5];
    const float* on_g = (const float*)d_in[6];
    const float* on_b = (const float*)d_in[7];
    const float* w_kv  = (const float*)d_in[8];
    const float* w_q   = (const float*)d_in[9];
    const float* w_out = (const float*)d_in[10];
    const float* gamma = (const float*)d_in[11];
    float* out = (float*)d_out;

    dim3 lnb(32, 8);
    const int attn_smem = ATTN_SMEM_FLOATS * 4;
    cudaFuncSetAttribute(attn_mma_kernel,
                         cudaFuncAttributeMaxDynamicSharedMemorySize, attn_smem);
    cudaFuncSetAttribute(wout_final_kernel,
                         cudaFuncAttributeMaxDynamicSharedMemorySize, WF_SMEM_BYTES);
    cudaFuncSetAttribute(kvsel_kernel,
                         cudaFuncAttributeMaxDynamicSharedMemorySize, KVSEL_SMEM_BYTES);

    zero_kernel<<<1024, 256>>>();
    prep_w<<<384, 256>>>(w_kv, w_q, w_out);
    ln_kernel<<<2048, lnb>>>(context, query_source, cn_g, cn_b, qn_g, qn_b);

    tgemm_kernel<<<dim3(32, 8, 8), 128>>>();   // K-stats (no store) + q

    score_kernel<<<64, 64>>>();
    kvsel_kernel<<<dim3(64, 2), 256, KVSEL_SMEM_BYTES>>>(w_kv);

    attn_mma_kernel<<<dim3(32, 64), 128, attn_smem>>>();

    wout_final_kernel<<<dim3(64, 1, 8), 256, WF_SMEM_BYTES>>>(
        query_source, on_g, on_b, gamma, out);
}

// round 15
// speedup vs baseline: 1.0382x; 1.0003x over previous
#include <cuda_runtime.h>
#include <math.h>
#include <stdint.h>

#define HW    4096
#define CDIM  256
#define BATCH 8
#define NBH   64     // B*HEADS
#define DH    64     // DIM_HEAD

// ---------------- scratch (device globals; no runtime allocation) ----------
__device__ float g_ctx[BATCH * CDIM * HW];        // layernormed context (tf32-rounded)
__device__ float g_qs [BATCH * CDIM * HW];        // layernormed query_source (tf32-rounded)
__device__ float g_q  [BATCH * 512  * HW];        // w_q output (l2-normalized)
__device__ float g_att[BATCH * 512  * HW];        // attention output (tf32-rounded)
__device__ float g_qprobe[NBH * DH];
__device__ float g_rowabs[NBH * DH * 64];         // [bh][d][h]
__device__ float g_colabs[NBH * DH * 64];         // [bh][d][w]
__device__ int   g_idxh[NBH * 8];
__device__ int   g_idxw[NBH * 8];
__device__ float g_kselT[NBH * 64 * DH];          // [bh][d][j]  (K^T for mma)
__device__ float g_vsel [NBH * 64 * DH];          // [bh][j][d]

// tf32-pre-rounded weights, packed in mma-fragment order:
// [mtile128][kt16][mblk16][ks8][lane32] -> float4 {A[m][k],A[m+8][k],A[m][k+4],A[m+8][k+4]}
__device__ float g_wkvp[512 * 256];               // K half only
__device__ float g_wqp [512 * 256];
__device__ float g_woutp[256 * 512];

__device__ __forceinline__ float tf32r(float x) {
    uint32_t u;
    asm("cvt.rna.tf32.f32 %0, %1;" : "=r"(u) : "f"(x));
    return __uint_as_float(u);
}

// ---------------- zero scratch reductions ----------------------------------
__global__ void zero_kernel() {
    int i = blockIdx.x * 256 + threadIdx.x;
    if (i < NBH * DH) g_qprobe[i] = 0.f;
    if (i < NBH * DH * 64) { g_rowabs[i] = 0.f; g_colabs[i] = 0.f; }
}

// ---------------- weight prep: tf32-round + pack into fragment order -------
__global__ void prep_w(const float* __restrict__ wkv,
                       const float* __restrict__ wq,
                       const float* __restrict__ wout) {
    int fid = blockIdx.x * 256 + threadIdx.x;
    const float* W; float4* Dst; int K, rel;
    if (fid < 32768)      { W = wkv;  Dst = (float4*)g_wkvp;  K = 256; rel = fid; }
    else if (fid < 65536) { W = wq;   Dst = (float4*)g_wqp;   K = 256; rel = fid - 32768; }
    else                  { W = wout; Dst = (float4*)g_woutp; K = 512; rel = fid - 65536; }
    int KT = K >> 4;
    int per_mtile = KT * 512;
    int mtile = rel / per_mtile;
    int r2 = rel - mtile * per_mtile;
    int kt = r2 >> 9;
    int sub = r2 & 511;
    int mblk = (sub >> 6) & 7;
    int ks = (sub >> 5) & 1;
    int lane = sub & 31;
    int gid = lane >> 2, tq = lane & 3;
    int m = mtile * 128 + mblk * 16 + gid;
    int k = kt * 16 + ks * 8 + tq;
    float4 v;
    v.x = tf32r(W[(size_t)m * K + k]);
    v.y = tf32r(W[(size_t)(m + 8) * K + k]);
    v.z = tf32r(W[(size_t)m * K + k + 4]);
    v.w = tf32r(W[(size_t)(m + 8) * K + k + 4]);
    Dst[rel] = v;
}

// ---------------- channel layernorm, both tensors in one launch ------------
__global__ void ln_kernel(const float* __restrict__ xc,
                          const float* __restrict__ xq,
                          const float* __restrict__ cg, const float* __restrict__ cb,
                          const float* __restrict__ qg, const float* __restrict__ qb) {
    int sel = blockIdx.x >> 10;
    const float* x  = sel ? xq : xc;
    const float* gw = sel ? qg : cg;
    const float* bw = sel ? qb : cb;
    float* out = sel ? g_qs : g_ctx;
    int tx = threadIdx.x, ty = threadIdx.y;
    int gp = (blockIdx.x & 1023) * 32 + tx;
    int bidx = gp >> 12;
    int p = gp & (HW - 1);
    size_t base = (size_t)bidx * CDIM * HW + p;

    float vals[32];
    float s = 0.f, s2 = 0.f;
#pragma unroll
    for (int i = 0; i < 32; i++) {
        int c = ty + i * 8;
        float v = x[base + (size_t)c * HW];
        vals[i] = v; s += v; s2 += v * v;
    }
    __shared__ float rs[8][32], rs2[8][32];
    rs[ty][tx] = s; rs2[ty][tx] = s2;
    __syncthreads();
    for (int st = 4; st > 0; st >>= 1) {
        if (ty < st) { rs[ty][tx] += rs[ty + st][tx]; rs2[ty][tx] += rs2[ty + st][tx]; }
        __syncthreads();
    }
    float mean = rs[0][tx] * (1.0f / CDIM);
    float var  = rs2[0][tx] * (1.0f / CDIM) - mean * mean;
    float inv  = rsqrtf(var + 1e-5f);
#pragma unroll
    for (int i = 0; i < 32; i++) {
        int c = ty + i * 8;
        out[base + (size_t)c * HW] = tf32r((vals[i] - mean) * inv * gw[c] + bw[c]);
    }
}

// ---------------- cp.async helpers -----------------------------------------
__device__ __forceinline__ void cpasync16(uint32_t smem, const void* g) {
    asm volatile("cp.async.cg.shared.global [%0], [%1], 16;\n" :: "r"(smem), "l"(g));
}
#define CP_COMMIT() asm volatile("cp.async.commit_group;\n" ::: "memory")
#define CP_WAIT1()  asm volatile("cp.async.wait_group 1;\n" ::: "memory")
#define CP_WAIT2()  asm volatile("cp.async.wait_group 2;\n" ::: "memory")

// ---------------- tensor-core GEMM: K-stats (no store) + q -----------------
// grid (32, 8, 8): y<4 -> K stats tile y (NO output store), y>=4 -> q tile.
// 128 threads / 4 warps (2x2), 64x64 warp tiles, 4-stage pipeline.
#define BS_STRIDE 136

__global__ void __launch_bounds__(128)
tgemm_kernel() {
    int by = blockIdx.y;
    int selEff;
    if (by < 4) selEff = 0;
    else { selEff = 1; by -= 4; }
    const uint4* Ap4; const float* Bp; float* Cp;
    if (selEff == 0) { Ap4 = (const uint4*)g_wkvp; Bp = g_ctx; Cp = nullptr; }
    else             { Ap4 = (const uint4*)g_wqp;  Bp = g_qs;  Cp = g_q;   }
    const int K = 256, KT = 16;
    Bp += (size_t)blockIdx.z * K * HW;
    if (Cp) Cp += (size_t)blockIdx.z * 512 * HW;
    Ap4 += (size_t)by * (KT * 512);

    __shared__ __align__(16) uint4 As4[4][512];
    __shared__ __align__(16) float Bs[4][16][BS_STRIDE];

    int m0 = by * 128, n0 = blockIdx.x * 128;
    int tid = threadIdx.x;
    int wid = tid >> 5, lane = tid & 31;
    int wm = wid >> 1, wn = wid & 1;
    int gid = lane >> 2, tq = lane & 3;

    int bk = tid >> 3;
    int bn = (tid & 7) * 16;

    auto load_stage = [&](int s, int kt) {
#pragma unroll
        for (int r = 0; r < 4; r++) {
            uint32_t adst = (uint32_t)__cvta_generic_to_shared(&As4[s][tid + r * 128]);
            cpasync16(adst, Ap4 + kt * 512 + tid + r * 128);
        }
        uint32_t bdst = (uint32_t)__cvta_generic_to_shared(&Bs[s][bk][bn]);
        const float* bsrc = Bp + (size_t)(kt * 16 + bk) * HW + n0 + bn;
#pragma unroll
        for (int r = 0; r < 4; r++)
            cpasync16(bdst + r * 16, bsrc + r * 4);
    };

    float acc[4][8][4];
#pragma unroll
    for (int i = 0; i < 4; i++)
#pragma unroll
        for (int n = 0; n < 8; n++)
#pragma unroll
            for (int r = 0; r < 4; r++) acc[i][n][r] = 0.f;

    load_stage(0, 0); CP_COMMIT();
    load_stage(1, 1); CP_COMMIT();
    load_stage(2, 2); CP_COMMIT();

    for (int kt = 0; kt < KT; kt++) {
        CP_WAIT2();
        __syncthreads();
        if (kt + 3 < KT) load_stage((kt + 3) & 3, kt + 3);
        CP_COMMIT();
        int s = kt & 3;

#pragma unroll
        for (int ks = 0; ks < 2; ks++) {
            int kk = ks * 8 + tq;
            uint4 af[4];
            uint32_t bf[8][2];
#pragma unroll
            for (int i = 0; i < 4; i++)
                af[i] = As4[s][(4 * wm + i) * 64 + ks * 32 + lane];
#pragma unroll
            for (int n = 0; n < 8; n++) {
                int c = wn * 64 + n * 8 + gid;
                bf[n][0] = __float_as_uint(Bs[s][kk][c]);
                bf[n][1] = __float_as_uint(Bs[s][kk + 4][c]);
            }
#pragma unroll
            for (int i = 0; i < 4; i++)
#pragma unroll
                for (int n = 0; n < 8; n++) {
                    asm volatile(
                        "mma.sync.aligned.m16n8k8.row.col.f32.tf32.tf32.f32 "
                        "{%0,%1,%2,%3}, {%4,%5,%6,%7}, {%8,%9}, {%0,%1,%2,%3};"
                        : "+f"(acc[i][n][0]), "+f"(acc[i][n][1]),
                          "+f"(acc[i][n][2]), "+f"(acc[i][n][3])
                        : "r"(af[i].x), "r"(af[i].y), "r"(af[i].z), "r"(af[i].w),
                          "r"(bf[n][0]), "r"(bf[n][1]));
                }
        }
    }

    float inv_c[8][2];
#pragma unroll
    for (int n = 0; n < 8; n++) {
        float s0 = 0.f, s1 = 0.f;
#pragma unroll
        for (int i = 0; i < 4; i++) {
            s0 += acc[i][n][0] * acc[i][n][0] + acc[i][n][2] * acc[i][n][2];
            s1 += acc[i][n][1] * acc[i][n][1] + acc[i][n][3] * acc[i][n][3];
        }
        s0 += __shfl_xor_sync(0xffffffffu, s0, 4);
        s0 += __shfl_xor_sync(0xffffffffu, s0, 8);
        s0 += __shfl_xor_sync(0xffffffffu, s0, 16);
        s1 += __shfl_xor_sync(0xffffffffu, s1, 4);
        s1 += __shfl_xor_sync(0xffffffffu, s1, 8);
        s1 += __shfl_xor_sync(0xffffffffu, s1, 16);
        inv_c[n][0] = 1.0f / fmaxf(sqrtf(s0), 1e-12f);
        inv_c[n][1] = 1.0f / fmaxf(sqrtf(s1), 1e-12f);
    }
#pragma unroll
    for (int i = 0; i < 4; i++)
#pragma unroll
        for (int n = 0; n < 8; n++) {
            acc[i][n][0] *= inv_c[n][0];
            acc[i][n][1] *= inv_c[n][1];
            acc[i][n][2] *= inv_c[n][0];
            acc[i][n][3] *= inv_c[n][1];
        }

    int head = by * 2 + wm;
    int bh = blockIdx.z * 8 + head;

    if (selEff == 1) {
#pragma unroll
        for (int i = 0; i < 4; i++) {
            float r0s = 0.f, r1s = 0.f;
#pragma unroll
            for (int n = 0; n < 8; n++) {
                r0s += acc[i][n][0] + acc[i][n][1];
                r1s += acc[i][n][2] + acc[i][n][3];
            }
            r0s += __shfl_xor_sync(0xffffffffu, r0s, 1);
            r0s += __shfl_xor_sync(0xffffffffu, r0s, 2);
            r1s += __shfl_xor_sync(0xffffffffu, r1s, 1);
            r1s += __shfl_xor_sync(0xffffffffu, r1s, 2);
            if (tq == 0) {
                atomicAdd(&g_qprobe[bh * 64 + i * 16 + gid], r0s);
                atomicAdd(&g_qprobe[bh * 64 + i * 16 + gid + 8], r1s);
            }
        }
#pragma unroll
        for (int i = 0; i < 4; i++) {
            int r = m0 + wm * 64 + i * 16 + gid;
#pragma unroll
            for (int n = 0; n < 8; n++) {
                int c = n0 + wn * 64 + n * 8 + 2 * tq;
                *(float2*)(Cp + (size_t)r * HW + c)       = make_float2(acc[i][n][0], acc[i][n][1]);
                *(float2*)(Cp + (size_t)(r + 8) * HW + c) = make_float2(acc[i][n][2], acc[i][n][3]);
            }
        }
    } else {
        int hrow = blockIdx.x * 2 + wn;
#pragma unroll
        for (int i = 0; i < 4; i++) {
            int d0 = i * 16 + gid;
            float r0s = 0.f, r1s = 0.f;
#pragma unroll
            for (int n = 0; n < 8; n++) {
                float a0 = fabsf(acc[i][n][0]), a1 = fabsf(acc[i][n][1]);
                float a2 = fabsf(acc[i][n][2]), a3 = fabsf(acc[i][n][3]);
                r0s += a0 + a1; r1s += a2 + a3;
                int w0 = n * 8 + 2 * tq;
                atomicAdd(&g_colabs[bh * 4096 + d0 * 64 + w0],           a0);
                atomicAdd(&g_colabs[bh * 4096 + d0 * 64 + w0 + 1],       a1);
                atomicAdd(&g_colabs[bh * 4096 + (d0 + 8) * 64 + w0],     a2);
                atomicAdd(&g_colabs[bh * 4096 + (d0 + 8) * 64 + w0 + 1], a3);
            }
            r0s += __shfl_xor_sync(0xffffffffu, r0s, 1);
            r0s += __shfl_xor_sync(0xffffffffu, r0s, 2);
            r1s += __shfl_xor_sync(0xffffffffu, r1s, 1);
            r1s += __shfl_xor_sync(0xffffffffu, r1s, 2);
            if (tq == 0) {
                atomicAdd(&g_rowabs[bh * 4096 + d0 * 64 + hrow],       r0s);
                atomicAdd(&g_rowabs[bh * 4096 + (d0 + 8) * 64 + hrow], r1s);
            }
        }
    }
}

// ---------------- scores + top-8 selection ---------------------------------
__global__ void score_kernel() {
    int bh = blockIdx.x;
    int t = threadIdx.x;
    __shared__ float qp[64], sc[64];
    qp[t] = g_qprobe[bh * 64 + t];
    __syncthreads();

    float s = 0.f;
    for (int d = 0; d < 64; d++) s += qp[d] * g_rowabs[bh * 4096 + d * 64 + t];
    sc[t] = s;
    __syncthreads();
    if (t == 0) {
        for (int it = 0; it < 8; it++) {
            int best = 0; float bv = sc[0];
            for (int h = 1; h < 64; h++) if (sc[h] > bv) { bv = sc[h]; best = h; }
            g_idxh[bh * 8 + it] = best; sc[best] = -3e38f;
        }
    }
    __syncthreads();

    float s2 = 0.f;
    for (int d = 0; d < 64; d++) s2 += qp[d] * g_colabs[bh * 4096 + d * 64 + t];
    sc[t] = s2;
    __syncthreads();
    if (t == 0) {
        for (int it = 0; it < 8; it++) {
            int best = 0; float bv = sc[0];
            for (int w = 1; w < 64; w++) if (sc[w] > bv) { bv = sc[w]; best = w; }
            g_idxw[bh * 8 + it] = best; sc[best] = -3e38f;
        }
    }
}

// ---------------- K/V at selected pixels (fp32, smem-staged) ---------------
#define KV_C_ST 257
#define KV_W_ST 68
#define KVSEL_SMEM_BYTES ((64 * KV_C_ST + 256 * KV_W_ST) * 4)

__global__ void __launch_bounds__(256)
kvsel_kernel(const float* __restrict__ wkv) {
    extern __shared__ float ksm[];
    float* csm = ksm;
    float* wsm = ksm + 64 * KV_C_ST;
    __shared__ int pix[64];

    int bh = blockIdx.x, isV = blockIdx.y;
    int b = bh >> 3, head = bh & 7;
    int t = threadIdx.x;
    if (t < 64) pix[t] = g_idxh[bh * 8 + (t >> 3)] * 64 + g_idxw[bh * 8 + (t & 7)];
    __syncthreads();

    const float* wv = wkv + (size_t)(isV * 512 + head * 64) * 256;
#pragma unroll 4
    for (int it = 0; it < 64; it++) {
        int idx = it * 256 + t;
        int d = idx >> 8, c = idx & 255;
        wsm[c * KV_W_ST + d] = wv[d * 256 + c];
    }
    const float* ctx = g_ctx + (size_t)b * CDIM * HW;
#pragma unroll 4
    for (int it = 0; it < 64; it++) {
        int idx = it * 256 + t;
        int j = idx >> 8, c = idx & 255;
        csm[j * KV_C_ST + c] = __ldg(ctx + (size_t)c * HW + pix[j]);
    }
    __syncthreads();

    int j = t >> 2, dq = t & 3;
    float acc[16];
#pragma unroll
    for (int i = 0; i < 16; i++) acc[i] = 0.f;
    const float* crow = csm + j * KV_C_ST;
#pragma unroll 4
    for (int c = 0; c < 256; c++) {
        float xv = crow[c];
        const float4* wr = (const float4*)(wsm + c * KV_W_ST + dq * 16);
        float4 w0 = wr[0], w1 = wr[1], w2 = wr[2], w3 = wr[3];
        acc[0]  += w0.x * xv; acc[1]  += w0.y * xv; acc[2]  += w0.z * xv; acc[3]  += w0.w * xv;
        acc[4]  += w1.x * xv; acc[5]  += w1.y * xv; acc[6]  += w1.z * xv; acc[7]  += w1.w * xv;
        acc[8]  += w2.x * xv; acc[9]  += w2.y * xv; acc[10] += w2.z * xv; acc[11] += w2.w * xv;
        acc[12] += w3.x * xv; acc[13] += w3.y * xv; acc[14] += w3.z * xv; acc[15] += w3.w * xv;
    }

    if (isV) {
#pragma unroll
        for (int i = 0; i < 16; i++)
            g_vsel[bh * 4096 + j * 64 + dq * 16 + i] = acc[i];
    } else {
        float s = 0.f;
#pragma unroll
        for (int i = 0; i < 16; i++) s += acc[i] * acc[i];
        s += __shfl_xor_sync(0xffffffffu, s, 1);
        s += __shfl_xor_sync(0xffffffffu, s, 2);
        float inv = 1.0f / fmaxf(sqrtf(s), 1e-12f);
#pragma unroll
        for (int i = 0; i < 16; i++)
            g_kselT[bh * 4096 + (dq * 16 + i) * 64 + j] = acc[i] * inv;
    }
}

// ---------------- tensor-core attention ------------------------------------
#define KT_ST 72
#define QS_ST 136
#define PS_ST 68
#define ATTN_SMEM_FLOATS (4608 + 4608 + 8704)

__global__ void __launch_bounds__(128)
attn_mma_kernel() {
    extern __shared__ float sm[];
    float* kst = sm;
    float* vs  = sm + 4608;
    float* qps = sm + 9216;

    int bh = blockIdx.y;
    int pix0 = blockIdx.x * 128;
    int tid = threadIdx.x, lane = tid & 31, w = tid >> 5;
    int gid = lane >> 2, tq = lane & 3;
    int m0w = w * 32;
    size_t qb = (size_t)bh * 64 * HW + pix0;

    for (int t = tid; t < 4096; t += 128) {
        int r = t >> 6, c = t & 63;
        kst[r * KT_ST + c] = tf32r(g_kselT[bh * 4096 + t]);
        vs [r * KT_ST + c] = tf32r(g_vsel [bh * 4096 + t]);
    }
    for (int r = 0; r < 64; r += 2) {
        int rr = r + (tid >> 6);
        int cc = tid & 63;
        qps[rr * QS_ST + cc]      = tf32r(g_q[qb + (size_t)rr * HW + cc]);
        qps[rr * QS_ST + cc + 64] = tf32r(g_q[qb + (size_t)rr * HW + cc + 64]);
    }
    __syncthreads();

    float accs[2][8][4];
#pragma unroll
    for (int i = 0; i < 2; i++)
#pragma unroll
        for (int n = 0; n < 8; n++)
#pragma unroll
            for (int r = 0; r < 4; r++) accs[i][n][r] = 0.f;

#pragma unroll
    for (int k = 0; k < 8; k++) {
        int kk = k * 8;
        uint32_t a[2][4], b[8][2];
#pragma unroll
        for (int i = 0; i < 2; i++) {
            int mc = m0w + i * 16 + gid;
            a[i][0] = __float_as_uint(qps[(kk + tq) * QS_ST + mc]);
            a[i][1] = __float_as_uint(qps[(kk + tq) * QS_ST + mc + 8]);
            a[i][2] = __float_as_uint(qps[(kk + tq + 4) * QS_ST + mc]);
            a[i][3] = __float_as_uint(qps[(kk + tq + 4) * QS_ST + mc + 8]);
        }
#pragma unroll
        for (int n = 0; n < 8; n++) {
            b[n][0] = __float_as_uint(kst[(kk + tq) * KT_ST + n * 8 + gid]);
            b[n][1] = __float_as_uint(kst[(kk + tq + 4) * KT_ST + n * 8 + gid]);
        }
#pragma unroll
        for (int i = 0; i < 2; i++)
#pragma unroll
            for (int n = 0; n < 8; n++)
                asm volatile(
                    "mma.sync.aligned.m16n8k8.row.col.f32.tf32.tf32.f32 "
                    "{%0,%1,%2,%3}, {%4,%5,%6,%7}, {%8,%9}, {%0,%1,%2,%3};"
                    : "+f"(accs[i][n][0]), "+f"(accs[i][n][1]),
                      "+f"(accs[i][n][2]), "+f"(accs[i][n][3])
                    : "r"(a[i][0]), "r"(a[i][1]), "r"(a[i][2]), "r"(a[i][3]),
                      "r"(b[n][0]), "r"(b[n][1]));
    }

    float inv0[2], inv1[2];
#pragma unroll
    for (int i = 0; i < 2; i++) {
        float mx0 = -3e38f, mx1 = -3e38f;
#pragma unroll
        for (int n = 0; n < 8; n++) {
            mx0 = fmaxf(mx0, fmaxf(accs[i][n][0], accs[i][n][1]));
            mx1 = fmaxf(mx1, fmaxf(accs[i][n][2], accs[i][n][3]));
        }
        mx0 = fmaxf(mx0, __shfl_xor_sync(0xffffffffu, mx0, 1));
        mx0 = fmaxf(mx0, __shfl_xor_sync(0xffffffffu, mx0, 2));
        mx1 = fmaxf(mx1, __shfl_xor_sync(0xffffffffu, mx1, 1));
        mx1 = fmaxf(mx1, __shfl_xor_sync(0xffffffffu, mx1, 2));
        float s0 = 0.f, s1 = 0.f;
#pragma unroll
        for (int n = 0; n < 8; n++) {
            accs[i][n][0] = __expf(accs[i][n][0] - mx0);
            accs[i][n][1] = __expf(accs[i][n][1] - mx0);
            accs[i][n][2] = __expf(accs[i][n][2] - mx1);
            accs[i][n][3] = __expf(accs[i][n][3] - mx1);
            s0 += accs[i][n][0] + accs[i][n][1];
            s1 += accs[i][n][2] + accs[i][n][3];
        }
        s0 += __shfl_xor_sync(0xffffffffu, s0, 1);
        s0 += __shfl_xor_sync(0xffffffffu, s0, 2);
        s1 += __shfl_xor_sync(0xffffffffu, s1, 1);
        s1 += __shfl_xor_sync(0xffffffffu, s1, 2);
        inv0[i] = 1.0f / s0;
        inv1[i] = 1.0f / s1;
    }

    __syncthreads();
    float* ps = qps;
#pragma unroll
    for (int i = 0; i < 2; i++) {
        int r0 = m0w + i * 16 + gid;
#pragma unroll
        for (int n = 0; n < 8; n++) {
            int c = n * 8 + 2 * tq;
            ps[r0 * PS_ST + c]           = tf32r(accs[i][n][0]);
            ps[r0 * PS_ST + c + 1]       = tf32r(accs[i][n][1]);
            ps[(r0 + 8) * PS_ST + c]     = tf32r(accs[i][n][2]);
            ps[(r0 + 8) * PS_ST + c + 1] = tf32r(accs[i][n][3]);
        }
    }

    float acco[2][8][4];
#pragma unroll
    for (int i = 0; i < 2; i++)
#pragma unroll
        for (int n = 0; n < 8; n++)
#pragma unroll
            for (int r = 0; r < 4; r++) acco[i][n][r] = 0.f;

#pragma unroll
    for (int k = 0; k < 8; k++) {
        int kk = k * 8;
        uint32_t a[2][4], b[8][2];
#pragma unroll
        for (int i = 0; i < 2; i++) {
            int r0 = m0w + i * 16 + gid;
            a[i][0] = __float_as_uint(ps[r0 * PS_ST + kk + tq]);
            a[i][1] = __float_as_uint(ps[(r0 + 8) * PS_ST + kk + tq]);
            a[i][2] = __float_as_uint(ps[r0 * PS_ST + kk + tq + 4]);
            a[i][3] = __float_as_uint(ps[(r0 + 8) * PS_ST + kk + tq + 4]);
        }
#pragma unroll
        for (int n = 0; n < 8; n++) {
            b[n][0] = __float_as_uint(vs[(kk + tq) * KT_ST + n * 8 + gid]);
            b[n][1] = __float_as_uint(vs[(kk + tq + 4) * KT_ST + n * 8 + gid]);
        }
#pragma unroll
        for (int i = 0; i < 2; i++)
#pragma unroll
            for (int n = 0; n < 8; n++)
                asm volatile(
                    "mma.sync.aligned.m16n8k8.row.col.f32.tf32.tf32.f32 "
                    "{%0,%1,%2,%3}, {%4,%5,%6,%7}, {%8,%9}, {%0,%1,%2,%3};"
                    : "+f"(acco[i][n][0]), "+f"(acco[i][n][1]),
                      "+f"(acco[i][n][2]), "+f"(acco[i][n][3])
                    : "r"(a[i][0]), "r"(a[i][1]), "r"(a[i][2]), "r"(a[i][3]),
                      "r"(b[n][0]), "r"(b[n][1]));
    }

    size_t ob = (size_t)bh * 64 * HW + pix0;
#pragma unroll
    for (int i = 0; i < 2; i++) {
        int prow = m0w + i * 16 + gid;
#pragma unroll
        for (int n = 0; n < 8; n++) {
            int d0 = n * 8 + 2 * tq;
            g_att[ob + (size_t)d0 * HW + prow]           = tf32r(acco[i][n][0] * inv0[i]);
            g_att[ob + (size_t)(d0 + 1) * HW + prow]     = tf32r(acco[i][n][1] * inv0[i]);
            g_att[ob + (size_t)d0 * HW + prow + 8]       = tf32r(acco[i][n][2] * inv1[i]);
            g_att[ob + (size_t)(d0 + 1) * HW + prow + 8] = tf32r(acco[i][n][3] * inv1[i]);
        }
    }
}

// ---------------- w_out GEMM + final LN + residual (128 thr, 3-stage) ------
// M=256 x N=64 pixels, K=512. 4 warps, each 64x64 (wm = warp row).
#define WF_BS_ST 72
#define WF_A_STAGE 1024                          // uint4 per stage
#define WF_AS_BYTES (3 * WF_A_STAGE * 16)        // 49152
#define WF_BS_BYTES (3 * 16 * WF_BS_ST * 4)      // 13824
#define WF_SMEM_BYTES (WF_AS_BYTES + WF_BS_BYTES + 4 * 64 * 4)

__global__ void __launch_bounds__(128, 3)
wout_final_kernel(const float* __restrict__ qsrc,
                  const float* __restrict__ gw,
                  const float* __restrict__ bw,
                  const float* __restrict__ gamma,
                  float* __restrict__ outp) {
    extern __shared__ char dsm[];
    uint4* As4 = (uint4*)dsm;                          // [3][1024]
    float* Bs  = (float*)(dsm + WF_AS_BYTES);          // [3][16][72]
    float* cs    = (float*)(dsm + WF_AS_BYTES + WF_BS_BYTES);
    float* cs2   = cs + 64;
    float* cmean = cs2 + 64;
    float* cinv  = cmean + 64;

    const uint4* Ap4 = (const uint4*)g_woutp;          // [mtile2][kt32][512]
    const float* Bp = g_att + (size_t)blockIdx.z * 512 * HW;
    int n0 = blockIdx.x * 64;
    int tid = threadIdx.x, lane = tid & 31;
    int wm = tid >> 5;                                 // 4 warp rows, 64 ch each
    int gid = lane >> 2, tq = lane & 3;

    int bk = tid >> 3;            // 0..15
    int bn = (tid & 7) * 8;       // 0..56

    auto load_stage = [&](int s, int kt) {
#pragma unroll
        for (int r = 0; r < 8; r++) {
            int idx = r * 128 + tid;
            int mt = idx >> 9, sub = idx & 511;
            uint32_t adst = (uint32_t)__cvta_generic_to_shared(&As4[s * WF_A_STAGE + idx]);
            cpasync16(adst, Ap4 + (size_t)mt * (32 * 512) + kt * 512 + sub);
        }
        uint32_t bdst = (uint32_t)__cvta_generic_to_shared(&Bs[(s * 16 + bk) * WF_BS_ST + bn]);
        const float* bsrc = Bp + (size_t)(kt * 16 + bk) * HW + n0 + bn;
        cpasync16(bdst, bsrc);
        cpasync16(bdst + 16, bsrc + 4);
    };

    float acc[4][8][4];
#pragma unroll
    for (int i = 0; i < 4; i++)
#pragma unroll
        for (int n = 0; n < 8; n++)
#pragma unroll
            for (int r = 0; r < 4; r++) acc[i][n][r] = 0.f;

    load_stage(0, 0); CP_COMMIT();
    load_stage(1, 1); CP_COMMIT();

    int mt = wm >> 1, mbb = (wm & 1) * 4;
    for (int kt = 0; kt < 32; kt++) {
        CP_WAIT1();
        __syncthreads();
        if (kt + 2 < 32) load_stage((kt + 2) % 3, kt + 2);
        CP_COMMIT();
        int s = kt % 3;

#pragma unroll
        for (int ks = 0; ks < 2; ks++) {
            int kk = ks * 8 + tq;
            uint4 af[4];
            uint32_t bf[8][2];
#pragma unroll
            for (int i = 0; i < 4; i++)
                af[i] = As4[s * WF_A_STAGE + mt * 512 + (mbb + i) * 64 + ks * 32 + lane];
#pragma unroll
            for (int n = 0; n < 8; n++) {
                int c = n * 8 + gid;
                bf[n][0] = __float_as_uint(Bs[(s * 16 + kk) * WF_BS_ST + c]);
                bf[n][1] = __float_as_uint(Bs[(s * 16 + kk + 4) * WF_BS_ST + c]);
            }
#pragma unroll
            for (int i = 0; i < 4; i++)
#pragma unroll
                for (int n = 0; n < 8; n++) {
                    asm volatile(
                        "mma.sync.aligned.m16n8k8.row.col.f32.tf32.tf32.f32 "
                        "{%0,%1,%2,%3}, {%4,%5,%6,%7}, {%8,%9}, {%0,%1,%2,%3};"
                        : "+f"(acc[i][n][0]), "+f"(acc[i][n][1]),
                          "+f"(acc[i][n][2]), "+f"(acc[i][n][3])
                        : "r"(af[i].x), "r"(af[i].y), "r"(af[i].z), "r"(af[i].w),
                          "r"(bf[n][0]), "r"(bf[n][1]));
                }
        }
    }

    // ---- per-pixel LN stats over all 256 channels ----
    if (tid < 64) { cs[tid] = 0.f; cs2[tid] = 0.f; }
    __syncthreads();
#pragma unroll
    for (int n = 0; n < 8; n++) {
        float s0 = 0.f, q0 = 0.f, s1 = 0.f, q1 = 0.f;
#pragma unroll
        for (int i = 0; i < 4; i++) {
            float a = acc[i][n][0], b2 = acc[i][n][2];
            s0 += a + b2; q0 += a * a + b2 * b2;
            float c1 = acc[i][n][1], d1 = acc[i][n][3];
            s1 += c1 + d1; q1 += c1 * c1 + d1 * d1;
        }
        s0 += __shfl_xor_sync(0xffffffffu, s0, 4);
        s0 += __shfl_xor_sync(0xffffffffu, s0, 8);
        s0 += __shfl_xor_sync(0xffffffffu, s0, 16);
        q0 += __shfl_xor_sync(0xffffffffu, q0, 4);
        q0 += __shfl_xor_sync(0xffffffffu, q0, 8);
        q0 += __shfl_xor_sync(0xffffffffu, q0, 16);
        s1 += __shfl_xor_sync(0xffffffffu, s1, 4);
        s1 += __shfl_xor_sync(0xffffffffu, s1, 8);
        s1 += __shfl_xor_sync(0xffffffffu, s1, 16);
        q1 += __shfl_xor_sync(0xffffffffu, q1, 4);
        q1 += __shfl_xor_sync(0xffffffffu, q1, 8);
        q1 += __shfl_xor_sync(0xffffffffu, q1, 16);
        if (gid == 0) {
            int c0 = n * 8 + 2 * tq;
            atomicAdd(&cs[c0], s0);  atomicAdd(&cs2[c0], q0);
            atomicAdd(&cs[c0 + 1], s1); atomicAdd(&cs2[c0 + 1], q1);
        }
    }
    __syncthreads();
    if (tid < 64) {
        float mean = cs[tid] * (1.0f / CDIM);
        float var  = cs2[tid] * (1.0f / CDIM) - mean * mean;
        cmean[tid] = mean;
        cinv[tid]  = rsqrtf(var + 1e-5f);
    }
    __syncthreads();

    float gm = gamma[0];
    size_t obase = (size_t)blockIdx.z * CDIM * HW;
#pragma unroll
    for (int i = 0; i < 4; i++) {
        int r = wm * 64 + i * 16 + gid;
        float g0 = gw[r], b0 = bw[r];
        float g1 = gw[r + 8], b1 = bw[r + 8];
#pragma unroll
        for (int n = 0; n < 8; n++) {
            int c = n * 8 + 2 * tq;
            int cg = n0 + c;
            float m0c = cmean[c], i0c = cinv[c];
            float m1c = cmean[c + 1], i1c = cinv[c + 1];
            float2 q0 = *(const float2*)(qsrc + obase + (size_t)r * HW + cg);
            float2 q1 = *(const float2*)(qsrc + obase + (size_t)(r + 8) * HW + cg);
            float2 o0, o1;
            o0.x = gm * ((acc[i][n][0] - m0c) * i0c * g0 + b0) + q0.x;
            o0.y = gm * ((acc[i][n][1] - m1c) * i1c * g0 + b0) + q0.y;
            o1.x = gm * ((acc[i][n][2] - m0c) * i0c * g1 + b1) + q1.x;
            o1.y = gm * ((acc[i][n][3] - m1c) * i1c * g1 + b1) + q1.y;
            *(float2*)(outp + obase + (size_t)r * HW + cg)       = o0;
            *(float2*)(outp + obase + (size_t)(r + 8) * HW + cg) = o1;
        }
    }
}

// ---------------- launch ----------------------------------------------------
extern "C" void kernel_launch(void* const* d_in, const int* in_sizes, int n_in,
                              void* d_out, int out_size) {
    const float* query_source = (const float*)d_in[0];
    const float* context      = (const float*)d_in[1];
    const float* cn_g = (const float*)d_in[2];
    const float* cn_b = (const float*)d_in[3];
    const float* qn_g = (const float*)d_in[4];
    const float* qn_b = (const float*)d_in[5];
    const float* on_g = (const float*)d_in[6];
    const float* on_b = (const float*)d_in[7];
    const float* w_kv  = (const float*)d_in[8];
    const float* w_q   = (const float*)d_in[9];
    const float* w_out = (const float*)d_in[10];
    const float* gamma = (const float*)d_in[11];
    float* out = (float*)d_out;

    dim3 lnb(32, 8);
    const int attn_smem = ATTN_SMEM_FLOATS * 4;
    cudaFuncSetAttribute(attn_mma_kernel,
                         cudaFuncAttributeMaxDynamicSharedMemorySize, attn_smem);
    cudaFuncSetAttribute(wout_final_kernel,
                         cudaFuncAttributeMaxDynamicSharedMemorySize, WF_SMEM_BYTES);
    cudaFuncSetAttribute(kvsel_kernel,
                         cudaFuncAttributeMaxDynamicSharedMemorySize, KVSEL_SMEM_BYTES);

    zero_kernel<<<1024, 256>>>();
    prep_w<<<384, 256>>>(w_kv, w_q, w_out);
    ln_kernel<<<2048, lnb>>>(context, query_source, cn_g, cn_b, qn_g, qn_b);

    tgemm_kernel<<<dim3(32, 8, 8), 128>>>();   // K-stats (no store) + q

    score_kernel<<<64, 64>>>();
    kvsel_kernel<<<dim3(64, 2), 256, KVSEL_SMEM_BYTES>>>(w_kv);

    attn_mma_kernel<<<dim3(32, 64), 128, attn_smem>>>();

    wout_final_kernel<<<dim3(64, 1, 8), 128, WF_SMEM_BYTES>>>(
        query_source, on_g, on_b, gamma, out);
}

// round 16
// speedup vs baseline: 1.0560x; 1.0171x over previous
#include <cuda_runtime.h>
#include <math.h>
#include <stdint.h>

#define HW    4096
#define CDIM  256
#define BATCH 8
#define NBH   64     // B*HEADS
#define DH    64     // DIM_HEAD

// ---------------- scratch (device globals; no runtime allocation) ----------
__device__ float g_ctx[BATCH * CDIM * HW];        // layernormed context (tf32-rounded)
__device__ float g_qs [BATCH * CDIM * HW];        // layernormed query_source (tf32-rounded)
__device__ float g_q  [BATCH * 512  * HW];        // w_q output (l2-normalized)
__device__ float g_att[BATCH * 512  * HW];        // attention output (tf32-rounded)
__device__ float g_qprobe[NBH * DH];
__device__ float g_rowabs[NBH * DH * 64];         // [bh][d][h]
__device__ float g_colabs[NBH * DH * 64];         // [bh][d][w]
__device__ int   g_idxh[NBH * 8];
__device__ int   g_idxw[NBH * 8];
__device__ float g_kselT[NBH * 64 * DH];          // [bh][d][j]  (K^T for mma)
__device__ float g_vsel [NBH * 64 * DH];          // [bh][j][d]

// tf32-pre-rounded weights, packed in mma-fragment order:
// [mtile128][kt16][mblk16][ks8][lane32] -> float4 {A[m][k],A[m+8][k],A[m][k+4],A[m+8][k+4]}
__device__ float g_wkvp[512 * 256];               // K half only
__device__ float g_wqp [512 * 256];
__device__ float g_woutp[256 * 512];

__device__ __forceinline__ float tf32r(float x) {
    uint32_t u;
    asm("cvt.rna.tf32.f32 %0, %1;" : "=r"(u) : "f"(x));
    return __uint_as_float(u);
}

// ---------------- zero scratch reductions ----------------------------------
__global__ void zero_kernel() {
    int i = blockIdx.x * 256 + threadIdx.x;
    if (i < NBH * DH) g_qprobe[i] = 0.f;
    if (i < NBH * DH * 64) { g_rowabs[i] = 0.f; g_colabs[i] = 0.f; }
}

// ---------------- weight prep: tf32-round + pack into fragment order -------
__global__ void prep_w(const float* __restrict__ wkv,
                       const float* __restrict__ wq,
                       const float* __restrict__ wout) {
    int fid = blockIdx.x * 256 + threadIdx.x;
    const float* W; float4* Dst; int K, rel;
    if (fid < 32768)      { W = wkv;  Dst = (float4*)g_wkvp;  K = 256; rel = fid; }
    else if (fid < 65536) { W = wq;   Dst = (float4*)g_wqp;   K = 256; rel = fid - 32768; }
    else                  { W = wout; Dst = (float4*)g_woutp; K = 512; rel = fid - 65536; }
    int KT = K >> 4;
    int per_mtile = KT * 512;
    int mtile = rel / per_mtile;
    int r2 = rel - mtile * per_mtile;
    int kt = r2 >> 9;
    int sub = r2 & 511;
    int mblk = (sub >> 6) & 7;
    int ks = (sub >> 5) & 1;
    int lane = sub & 31;
    int gid = lane >> 2, tq = lane & 3;
    int m = mtile * 128 + mblk * 16 + gid;
    int k = kt * 16 + ks * 8 + tq;
    float4 v;
    v.x = tf32r(W[(size_t)m * K + k]);
    v.y = tf32r(W[(size_t)(m + 8) * K + k]);
    v.z = tf32r(W[(size_t)m * K + k + 4]);
    v.w = tf32r(W[(size_t)(m + 8) * K + k + 4]);
    Dst[rel] = v;
}

// ---------------- channel layernorm, both tensors in one launch ------------
__global__ void ln_kernel(const float* __restrict__ xc,
                          const float* __restrict__ xq,
                          const float* __restrict__ cg, const float* __restrict__ cb,
                          const float* __restrict__ qg, const float* __restrict__ qb) {
    int sel = blockIdx.x >> 10;
    const float* x  = sel ? xq : xc;
    const float* gw = sel ? qg : cg;
    const float* bw = sel ? qb : cb;
    float* out = sel ? g_qs : g_ctx;
    int tx = threadIdx.x, ty = threadIdx.y;
    int gp = (blockIdx.x & 1023) * 32 + tx;
    int bidx = gp >> 12;
    int p = gp & (HW - 1);
    size_t base = (size_t)bidx * CDIM * HW + p;

    float vals[32];
    float s = 0.f, s2 = 0.f;
#pragma unroll
    for (int i = 0; i < 32; i++) {
        int c = ty + i * 8;
        float v = x[base + (size_t)c * HW];
        vals[i] = v; s += v; s2 += v * v;
    }
    __shared__ float rs[8][32], rs2[8][32];
    rs[ty][tx] = s; rs2[ty][tx] = s2;
    __syncthreads();
    for (int st = 4; st > 0; st >>= 1) {
        if (ty < st) { rs[ty][tx] += rs[ty + st][tx]; rs2[ty][tx] += rs2[ty + st][tx]; }
        __syncthreads();
    }
    float mean = rs[0][tx] * (1.0f / CDIM);
    float var  = rs2[0][tx] * (1.0f / CDIM) - mean * mean;
    float inv  = rsqrtf(var + 1e-5f);
#pragma unroll
    for (int i = 0; i < 32; i++) {
        int c = ty + i * 8;
        out[base + (size_t)c * HW] = tf32r((vals[i] - mean) * inv * gw[c] + bw[c]);
    }
}

// ---------------- cp.async helpers -----------------------------------------
__device__ __forceinline__ void cpasync16(uint32_t smem, const void* g) {
    asm volatile("cp.async.cg.shared.global [%0], [%1], 16;\n" :: "r"(smem), "l"(g));
}
#define CP_COMMIT() asm volatile("cp.async.commit_group;\n" ::: "memory")
#define CP_WAIT1()  asm volatile("cp.async.wait_group 1;\n" ::: "memory")
#define CP_WAIT2()  asm volatile("cp.async.wait_group 2;\n" ::: "memory")

// ---------------- tensor-core GEMM: K-stats (no store) + q -----------------
// grid (32, 8, 8): y<4 -> K stats tile y (NO output store), y>=4 -> q tile.
// 128 threads / 4 warps (2x2), 64x64 warp tiles, 4-stage pipeline.
// Round 16: fragments for BOTH ks steps loaded up front (needs reg headroom
// -> __launch_bounds__(128,2)); MMA order per accumulator unchanged.
#define BS_STRIDE 136

__global__ void __launch_bounds__(128, 2)
tgemm_kernel() {
    int by = blockIdx.y;
    int selEff;
    if (by < 4) selEff = 0;
    else { selEff = 1; by -= 4; }
    const uint4* Ap4; const float* Bp; float* Cp;
    if (selEff == 0) { Ap4 = (const uint4*)g_wkvp; Bp = g_ctx; Cp = nullptr; }
    else             { Ap4 = (const uint4*)g_wqp;  Bp = g_qs;  Cp = g_q;   }
    const int KT = 16;
    const int K = 256;
    Bp += (size_t)blockIdx.z * K * HW;
    if (Cp) Cp += (size_t)blockIdx.z * 512 * HW;
    Ap4 += (size_t)by * (KT * 512);

    __shared__ __align__(16) uint4 As4[4][512];
    __shared__ __align__(16) float Bs[4][16][BS_STRIDE];

    int m0 = by * 128, n0 = blockIdx.x * 128;
    int tid = threadIdx.x;
    int wid = tid >> 5, lane = tid & 31;
    int wm = wid >> 1, wn = wid & 1;
    int gid = lane >> 2, tq = lane & 3;

    int bk = tid >> 3;
    int bn = (tid & 7) * 16;

    auto load_stage = [&](int s, int kt) {
#pragma unroll
        for (int r = 0; r < 4; r++) {
            uint32_t adst = (uint32_t)__cvta_generic_to_shared(&As4[s][tid + r * 128]);
            cpasync16(adst, Ap4 + kt * 512 + tid + r * 128);
        }
        uint32_t bdst = (uint32_t)__cvta_generic_to_shared(&Bs[s][bk][bn]);
        const float* bsrc = Bp + (size_t)(kt * 16 + bk) * HW + n0 + bn;
#pragma unroll
        for (int r = 0; r < 4; r++)
            cpasync16(bdst + r * 16, bsrc + r * 4);
    };

    float acc[4][8][4];
#pragma unroll
    for (int i = 0; i < 4; i++)
#pragma unroll
        for (int n = 0; n < 8; n++)
#pragma unroll
            for (int r = 0; r < 4; r++) acc[i][n][r] = 0.f;

    load_stage(0, 0); CP_COMMIT();
    load_stage(1, 1); CP_COMMIT();
    load_stage(2, 2); CP_COMMIT();

    for (int kt = 0; kt < KT; kt++) {
        CP_WAIT2();
        __syncthreads();
        if (kt + 3 < KT) load_stage((kt + 3) & 3, kt + 3);
        CP_COMMIT();
        int s = kt & 3;

        // ---- load ALL fragments for both ks steps, then run all MMAs ----
        uint4 af2[2][4];
        uint32_t bf2[2][8][2];
#pragma unroll
        for (int ks = 0; ks < 2; ks++) {
            int kk = ks * 8 + tq;
#pragma unroll
            for (int i = 0; i < 4; i++)
                af2[ks][i] = As4[s][(4 * wm + i) * 64 + ks * 32 + lane];
#pragma unroll
            for (int n = 0; n < 8; n++) {
                int c = wn * 64 + n * 8 + gid;
                bf2[ks][n][0] = __float_as_uint(Bs[s][kk][c]);
                bf2[ks][n][1] = __float_as_uint(Bs[s][kk + 4][c]);
            }
        }
#pragma unroll
        for (int ks = 0; ks < 2; ks++)
#pragma unroll
            for (int i = 0; i < 4; i++)
#pragma unroll
                for (int n = 0; n < 8; n++) {
                    asm volatile(
                        "mma.sync.aligned.m16n8k8.row.col.f32.tf32.tf32.f32 "
                        "{%0,%1,%2,%3}, {%4,%5,%6,%7}, {%8,%9}, {%0,%1,%2,%3};"
                        : "+f"(acc[i][n][0]), "+f"(acc[i][n][1]),
                          "+f"(acc[i][n][2]), "+f"(acc[i][n][3])
                        : "r"(af2[ks][i].x), "r"(af2[ks][i].y),
                          "r"(af2[ks][i].z), "r"(af2[ks][i].w),
                          "r"(bf2[ks][n][0]), "r"(bf2[ks][n][1]));
                }
    }

    float inv_c[8][2];
#pragma unroll
    for (int n = 0; n < 8; n++) {
        float s0 = 0.f, s1 = 0.f;
#pragma unroll
        for (int i = 0; i < 4; i++) {
            s0 += acc[i][n][0] * acc[i][n][0] + acc[i][n][2] * acc[i][n][2];
            s1 += acc[i][n][1] * acc[i][n][1] + acc[i][n][3] * acc[i][n][3];
        }
        s0 += __shfl_xor_sync(0xffffffffu, s0, 4);
        s0 += __shfl_xor_sync(0xffffffffu, s0, 8);
        s0 += __shfl_xor_sync(0xffffffffu, s0, 16);
        s1 += __shfl_xor_sync(0xffffffffu, s1, 4);
        s1 += __shfl_xor_sync(0xffffffffu, s1, 8);
        s1 += __shfl_xor_sync(0xffffffffu, s1, 16);
        inv_c[n][0] = 1.0f / fmaxf(sqrtf(s0), 1e-12f);
        inv_c[n][1] = 1.0f / fmaxf(sqrtf(s1), 1e-12f);
    }
#pragma unroll
    for (int i = 0; i < 4; i++)
#pragma unroll
        for (int n = 0; n < 8; n++) {
            acc[i][n][0] *= inv_c[n][0];
            acc[i][n][1] *= inv_c[n][1];
            acc[i][n][2] *= inv_c[n][0];
            acc[i][n][3] *= inv_c[n][1];
        }

    int head = by * 2 + wm;
    int bh = blockIdx.z * 8 + head;

    if (selEff == 1) {
#pragma unroll
        for (int i = 0; i < 4; i++) {
            float r0s = 0.f, r1s = 0.f;
#pragma unroll
            for (int n = 0; n < 8; n++) {
                r0s += acc[i][n][0] + acc[i][n][1];
                r1s += acc[i][n][2] + acc[i][n][3];
            }
            r0s += __shfl_xor_sync(0xffffffffu, r0s, 1);
            r0s += __shfl_xor_sync(0xffffffffu, r0s, 2);
            r1s += __shfl_xor_sync(0xffffffffu, r1s, 1);
            r1s += __shfl_xor_sync(0xffffffffu, r1s, 2);
            if (tq == 0) {
                atomicAdd(&g_qprobe[bh * 64 + i * 16 + gid], r0s);
                atomicAdd(&g_qprobe[bh * 64 + i * 16 + gid + 8], r1s);
            }
        }
#pragma unroll
        for (int i = 0; i < 4; i++) {
            int r = m0 + wm * 64 + i * 16 + gid;
#pragma unroll
            for (int n = 0; n < 8; n++) {
                int c = n0 + wn * 64 + n * 8 + 2 * tq;
                *(float2*)(Cp + (size_t)r * HW + c)       = make_float2(acc[i][n][0], acc[i][n][1]);
                *(float2*)(Cp + (size_t)(r + 8) * HW + c) = make_float2(acc[i][n][2], acc[i][n][3]);
            }
        }
    } else {
        int hrow = blockIdx.x * 2 + wn;
#pragma unroll
        for (int i = 0; i < 4; i++) {
            int d0 = i * 16 + gid;
            float r0s = 0.f, r1s = 0.f;
#pragma unroll
            for (int n = 0; n < 8; n++) {
                float a0 = fabsf(acc[i][n][0]), a1 = fabsf(acc[i][n][1]);
                float a2 = fabsf(acc[i][n][2]), a3 = fabsf(acc[i][n][3]);
                r0s += a0 + a1; r1s += a2 + a3;
                int w0 = n * 8 + 2 * tq;
                atomicAdd(&g_colabs[bh * 4096 + d0 * 64 + w0],           a0);
                atomicAdd(&g_colabs[bh * 4096 + d0 * 64 + w0 + 1],       a1);
                atomicAdd(&g_colabs[bh * 4096 + (d0 + 8) * 64 + w0],     a2);
                atomicAdd(&g_colabs[bh * 4096 + (d0 + 8) * 64 + w0 + 1], a3);
            }
            r0s += __shfl_xor_sync(0xffffffffu, r0s, 1);
            r0s += __shfl_xor_sync(0xffffffffu, r0s, 2);
            r1s += __shfl_xor_sync(0xffffffffu, r1s, 1);
            r1s += __shfl_xor_sync(0xffffffffu, r1s, 2);
            if (tq == 0) {
                atomicAdd(&g_rowabs[bh * 4096 + d0 * 64 + hrow],       r0s);
                atomicAdd(&g_rowabs[bh * 4096 + (d0 + 8) * 64 + hrow], r1s);
            }
        }
    }
}

// ---------------- scores + top-8 selection ---------------------------------
__global__ void score_kernel() {
    int bh = blockIdx.x;
    int t = threadIdx.x;
    __shared__ float qp[64], sc[64];
    qp[t] = g_qprobe[bh * 64 + t];
    __syncthreads();

    float s = 0.f;
    for (int d = 0; d < 64; d++) s += qp[d] * g_rowabs[bh * 4096 + d * 64 + t];
    sc[t] = s;
    __syncthreads();
    if (t == 0) {
        for (int it = 0; it < 8; it++) {
            int best = 0; float bv = sc[0];
            for (int h = 1; h < 64; h++) if (sc[h] > bv) { bv = sc[h]; best = h; }
            g_idxh[bh * 8 + it] = best; sc[best] = -3e38f;
        }
    }
    __syncthreads();

    float s2 = 0.f;
    for (int d = 0; d < 64; d++) s2 += qp[d] * g_colabs[bh * 4096 + d * 64 + t];
    sc[t] = s2;
    __syncthreads();
    if (t == 0) {
        for (int it = 0; it < 8; it++) {
            int best = 0; float bv = sc[0];
            for (int w = 1; w < 64; w++) if (sc[w] > bv) { bv = sc[w]; best = w; }
            g_idxw[bh * 8 + it] = best; sc[best] = -3e38f;
        }
    }
}

// ---------------- K/V at selected pixels (fp32, smem-staged) ---------------
#define KV_C_ST 257
#define KV_W_ST 68
#define KVSEL_SMEM_BYTES ((64 * KV_C_ST + 256 * KV_W_ST) * 4)

__global__ void __launch_bounds__(256)
kvsel_kernel(const float* __restrict__ wkv) {
    extern __shared__ float ksm[];
    float* csm = ksm;
    float* wsm = ksm + 64 * KV_C_ST;
    __shared__ int pix[64];

    int bh = blockIdx.x, isV = blockIdx.y;
    int b = bh >> 3, head = bh & 7;
    int t = threadIdx.x;
    if (t < 64) pix[t] = g_idxh[bh * 8 + (t >> 3)] * 64 + g_idxw[bh * 8 + (t & 7)];
    __syncthreads();

    const float* wv = wkv + (size_t)(isV * 512 + head * 64) * 256;
#pragma unroll 4
    for (int it = 0; it < 64; it++) {
        int idx = it * 256 + t;
        int d = idx >> 8, c = idx & 255;
        wsm[c * KV_W_ST + d] = wv[d * 256 + c];
    }
    const float* ctx = g_ctx + (size_t)b * CDIM * HW;
#pragma unroll 4
    for (int it = 0; it < 64; it++) {
        int idx = it * 256 + t;
        int j = idx >> 8, c = idx & 255;
        csm[j * KV_C_ST + c] = __ldg(ctx + (size_t)c * HW + pix[j]);
    }
    __syncthreads();

    int j = t >> 2, dq = t & 3;
    float acc[16];
#pragma unroll
    for (int i = 0; i < 16; i++) acc[i] = 0.f;
    const float* crow = csm + j * KV_C_ST;
#pragma unroll 4
    for (int c = 0; c < 256; c++) {
        float xv = crow[c];
        const float4* wr = (const float4*)(wsm + c * KV_W_ST + dq * 16);
        float4 w0 = wr[0], w1 = wr[1], w2 = wr[2], w3 = wr[3];
        acc[0]  += w0.x * xv; acc[1]  += w0.y * xv; acc[2]  += w0.z * xv; acc[3]  += w0.w * xv;
        acc[4]  += w1.x * xv; acc[5]  += w1.y * xv; acc[6]  += w1.z * xv; acc[7]  += w1.w * xv;
        acc[8]  += w2.x * xv; acc[9]  += w2.y * xv; acc[10] += w2.z * xv; acc[11] += w2.w * xv;
        acc[12] += w3.x * xv; acc[13] += w3.y * xv; acc[14] += w3.z * xv; acc[15] += w3.w * xv;
    }

    if (isV) {
#pragma unroll
        for (int i = 0; i < 16; i++)
            g_vsel[bh * 4096 + j * 64 + dq * 16 + i] = acc[i];
    } else {
        float s = 0.f;
#pragma unroll
        for (int i = 0; i < 16; i++) s += acc[i] * acc[i];
        s += __shfl_xor_sync(0xffffffffu, s, 1);
        s += __shfl_xor_sync(0xffffffffu, s, 2);
        float inv = 1.0f / fmaxf(sqrtf(s), 1e-12f);
#pragma unroll
        for (int i = 0; i < 16; i++)
            g_kselT[bh * 4096 + (dq * 16 + i) * 64 + j] = acc[i] * inv;
    }
}

// ---------------- tensor-core attention ------------------------------------
#define KT_ST 72
#define QS_ST 136
#define PS_ST 68
#define ATTN_SMEM_FLOATS (4608 + 4608 + 8704)

__global__ void __launch_bounds__(128)
attn_mma_kernel() {
    extern __shared__ float sm[];
    float* kst = sm;
    float* vs  = sm + 4608;
    float* qps = sm + 9216;

    int bh = blockIdx.y;
    int pix0 = blockIdx.x * 128;
    int tid = threadIdx.x, lane = tid & 31, w = tid >> 5;
    int gid = lane >> 2, tq = lane & 3;
    int m0w = w * 32;
    size_t qb = (size_t)bh * 64 * HW + pix0;

    for (int t = tid; t < 4096; t += 128) {
        int r = t >> 6, c = t & 63;
        kst[r * KT_ST + c] = tf32r(g_kselT[bh * 4096 + t]);
        vs [r * KT_ST + c] = tf32r(g_vsel [bh * 4096 + t]);
    }
    for (int r = 0; r < 64; r += 2) {
        int rr = r + (tid >> 6);
        int cc = tid & 63;
        qps[rr * QS_ST + cc]      = tf32r(g_q[qb + (size_t)rr * HW + cc]);
        qps[rr * QS_ST + cc + 64] = tf32r(g_q[qb + (size_t)rr * HW + cc + 64]);
    }
    __syncthreads();

    float accs[2][8][4];
#pragma unroll
    for (int i = 0; i < 2; i++)
#pragma unroll
        for (int n = 0; n < 8; n++)
#pragma unroll
            for (int r = 0; r < 4; r++) accs[i][n][r] = 0.f;

#pragma unroll
    for (int k = 0; k < 8; k++) {
        int kk = k * 8;
        uint32_t a[2][4], b[8][2];
#pragma unroll
        for (int i = 0; i < 2; i++) {
            int mc = m0w + i * 16 + gid;
            a[i][0] = __float_as_uint(qps[(kk + tq) * QS_ST + mc]);
            a[i][1] = __float_as_uint(qps[(kk + tq) * QS_ST + mc + 8]);
            a[i][2] = __float_as_uint(qps[(kk + tq + 4) * QS_ST + mc]);
            a[i][3] = __float_as_uint(qps[(kk + tq + 4) * QS_ST + mc + 8]);
        }
#pragma unroll
        for (int n = 0; n < 8; n++) {
            b[n][0] = __float_as_uint(kst[(kk + tq) * KT_ST + n * 8 + gid]);
            b[n][1] = __float_as_uint(kst[(kk + tq + 4) * KT_ST + n * 8 + gid]);
        }
#pragma unroll
        for (int i = 0; i < 2; i++)
#pragma unroll
            for (int n = 0; n < 8; n++)
                asm volatile(
                    "mma.sync.aligned.m16n8k8.row.col.f32.tf32.tf32.f32 "
                    "{%0,%1,%2,%3}, {%4,%5,%6,%7}, {%8,%9}, {%0,%1,%2,%3};"
                    : "+f"(accs[i][n][0]), "+f"(accs[i][n][1]),
                      "+f"(accs[i][n][2]), "+f"(accs[i][n][3])
                    : "r"(a[i][0]), "r"(a[i][1]), "r"(a[i][2]), "r"(a[i][3]),
                      "r"(b[n][0]), "r"(b[n][1]));
    }

    float inv0[2], inv1[2];
#pragma unroll
    for (int i = 0; i < 2; i++) {
        float mx0 = -3e38f, mx1 = -3e38f;
#pragma unroll
        for (int n = 0; n < 8; n++) {
            mx0 = fmaxf(mx0, fmaxf(accs[i][n][0], accs[i][n][1]));
            mx1 = fmaxf(mx1, fmaxf(accs[i][n][2], accs[i][n][3]));
        }
        mx0 = fmaxf(mx0, __shfl_xor_sync(0xffffffffu, mx0, 1));
        mx0 = fmaxf(mx0, __shfl_xor_sync(0xffffffffu, mx0, 2));
        mx1 = fmaxf(mx1, __shfl_xor_sync(0xffffffffu, mx1, 1));
        mx1 = fmaxf(mx1, __shfl_xor_sync(0xffffffffu, mx1, 2));
        float s0 = 0.f, s1 = 0.f;
#pragma unroll
        for (int n = 0; n < 8; n++) {
            accs[i][n][0] = __expf(accs[i][n][0] - mx0);
            accs[i][n][1] = __expf(accs[i][n][1] - mx0);
            accs[i][n][2] = __expf(accs[i][n][2] - mx1);
            accs[i][n][3] = __expf(accs[i][n][3] - mx1);
            s0 += accs[i][n][0] + accs[i][n][1];
            s1 += accs[i][n][2] + accs[i][n][3];
        }
        s0 += __shfl_xor_sync(0xffffffffu, s0, 1);
        s0 += __shfl_xor_sync(0xffffffffu, s0, 2);
        s1 += __shfl_xor_sync(0xffffffffu, s1, 1);
        s1 += __shfl_xor_sync(0xffffffffu, s1, 2);
        inv0[i] = 1.0f / s0;
        inv1[i] = 1.0f / s1;
    }

    __syncthreads();
    float* ps = qps;
#pragma unroll
    for (int i = 0; i < 2; i++) {
        int r0 = m0w + i * 16 + gid;
#pragma unroll
        for (int n = 0; n < 8; n++) {
            int c = n * 8 + 2 * tq;
            ps[r0 * PS_ST + c]           = tf32r(accs[i][n][0]);
            ps[r0 * PS_ST + c + 1]       = tf32r(accs[i][n][1]);
            ps[(r0 + 8) * PS_ST + c]     = tf32r(accs[i][n][2]);
            ps[(r0 + 8) * PS_ST + c + 1] = tf32r(accs[i][n][3]);
        }
    }

    float acco[2][8][4];
#pragma unroll
    for (int i = 0; i < 2; i++)
#pragma unroll
        for (int n = 0; n < 8; n++)
#pragma unroll
            for (int r = 0; r < 4; r++) acco[i][n][r] = 0.f;

#pragma unroll
    for (int k = 0; k < 8; k++) {
        int kk = k * 8;
        uint32_t a[2][4], b[8][2];
#pragma unroll
        for (int i = 0; i < 2; i++) {
            int r0 = m0w + i * 16 + gid;
            a[i][0] = __float_as_uint(ps[r0 * PS_ST + kk + tq]);
            a[i][1] = __float_as_uint(ps[(r0 + 8) * PS_ST + kk + tq]);
            a[i][2] = __float_as_uint(ps[r0 * PS_ST + kk + tq + 4]);
            a[i][3] = __float_as_uint(ps[(r0 + 8) * PS_ST + kk + tq + 4]);
        }
#pragma unroll
        for (int n = 0; n < 8; n++) {
            b[n][0] = __float_as_uint(vs[(kk + tq) * KT_ST + n * 8 + gid]);
            b[n][1] = __float_as_uint(vs[(kk + tq + 4) * KT_ST + n * 8 + gid]);
        }
#pragma unroll
        for (int i = 0; i < 2; i++)
#pragma unroll
            for (int n = 0; n < 8; n++)
                asm volatile(
                    "mma.sync.aligned.m16n8k8.row.col.f32.tf32.tf32.f32 "
                    "{%0,%1,%2,%3}, {%4,%5,%6,%7}, {%8,%9}, {%0,%1,%2,%3};"
                    : "+f"(acco[i][n][0]), "+f"(acco[i][n][1]),
                      "+f"(acco[i][n][2]), "+f"(acco[i][n][3])
                    : "r"(a[i][0]), "r"(a[i][1]), "r"(a[i][2]), "r"(a[i][3]),
                      "r"(b[n][0]), "r"(b[n][1]));
    }

    size_t ob = (size_t)bh * 64 * HW + pix0;
#pragma unroll
    for (int i = 0; i < 2; i++) {
        int prow = m0w + i * 16 + gid;
#pragma unroll
        for (int n = 0; n < 8; n++) {
            int d0 = n * 8 + 2 * tq;
            g_att[ob + (size_t)d0 * HW + prow]           = tf32r(acco[i][n][0] * inv0[i]);
            g_att[ob + (size_t)(d0 + 1) * HW + prow]     = tf32r(acco[i][n][1] * inv0[i]);
            g_att[ob + (size_t)d0 * HW + prow + 8]       = tf32r(acco[i][n][2] * inv1[i]);
            g_att[ob + (size_t)(d0 + 1) * HW + prow + 8] = tf32r(acco[i][n][3] * inv1[i]);
        }
    }
}

// ---------------- w_out GEMM + final LN + residual (128 thr, 3-stage) ------
#define WF_BS_ST 72
#define WF_A_STAGE 1024
#define WF_AS_BYTES (3 * WF_A_STAGE * 16)
#define WF_BS_BYTES (3 * 16 * WF_BS_ST * 4)
#define WF_SMEM_BYTES (WF_AS_BYTES + WF_BS_BYTES + 4 * 64 * 4)

__global__ void __launch_bounds__(128, 3)
wout_final_kernel(const float* __restrict__ qsrc,
                  const float* __restrict__ gw,
                  const float* __restrict__ bw,
                  const float* __restrict__ gamma,
                  float* __restrict__ outp) {
    extern __shared__ char dsm[];
    uint4* As4 = (uint4*)dsm;
    float* Bs  = (float*)(dsm + WF_AS_BYTES);
    float* cs    = (float*)(dsm + WF_AS_BYTES + WF_BS_BYTES);
    float* cs2   = cs + 64;
    float* cmean = cs2 + 64;
    float* cinv  = cmean + 64;

    const uint4* Ap4 = (const uint4*)g_woutp;
    const float* Bp = g_att + (size_t)blockIdx.z * 512 * HW;
    int n0 = blockIdx.x * 64;
    int tid = threadIdx.x, lane = tid & 31;
    int wm = tid >> 5;
    int gid = lane >> 2, tq = lane & 3;

    int bk = tid >> 3;
    int bn = (tid & 7) * 8;

    auto load_stage = [&](int s, int kt) {
#pragma unroll
        for (int r = 0; r < 8; r++) {
            int idx = r * 128 + tid;
            int mt = idx >> 9, sub = idx & 511;
            uint32_t adst = (uint32_t)__cvta_generic_to_shared(&As4[s * WF_A_STAGE + idx]);
            cpasync16(adst, Ap4 + (size_t)mt * (32 * 512) + kt * 512 + sub);
        }
        uint32_t bdst = (uint32_t)__cvta_generic_to_shared(&Bs[(s * 16 + bk) * WF_BS_ST + bn]);
        const float* bsrc = Bp + (size_t)(kt * 16 + bk) * HW + n0 + bn;
        cpasync16(bdst, bsrc);
        cpasync16(bdst + 16, bsrc + 4);
    };

    float acc[4][8][4];
#pragma unroll
    for (int i = 0; i < 4; i++)
#pragma unroll
        for (int n = 0; n < 8; n++)
#pragma unroll
            for (int r = 0; r < 4; r++) acc[i][n][r] = 0.f;

    load_stage(0, 0); CP_COMMIT();
    load_stage(1, 1); CP_COMMIT();

    int mt = wm >> 1, mbb = (wm & 1) * 4;
    for (int kt = 0; kt < 32; kt++) {
        CP_WAIT1();
        __syncthreads();
        if (kt + 2 < 32) load_stage((kt + 2) % 3, kt + 2);
        CP_COMMIT();
        int s = kt % 3;

#pragma unroll
        for (int ks = 0; ks < 2; ks++) {
            int kk = ks * 8 + tq;
            uint4 af[4];
            uint32_t bf[8][2];
#pragma unroll
            for (int i = 0; i < 4; i++)
                af[i] = As4[s * WF_A_STAGE + mt * 512 + (mbb + i) * 64 + ks * 32 + lane];
#pragma unroll
            for (int n = 0; n < 8; n++) {
                int c = n * 8 + gid;
                bf[n][0] = __float_as_uint(Bs[(s * 16 + kk) * WF_BS_ST + c]);
                bf[n][1] = __float_as_uint(Bs[(s * 16 + kk + 4) * WF_BS_ST + c]);
            }
#pragma unroll
            for (int i = 0; i < 4; i++)
#pragma unroll
                for (int n = 0; n < 8; n++) {
                    asm volatile(
                        "mma.sync.aligned.m16n8k8.row.col.f32.tf32.tf32.f32 "
                        "{%0,%1,%2,%3}, {%4,%5,%6,%7}, {%8,%9}, {%0,%1,%2,%3};"
                        : "+f"(acc[i][n][0]), "+f"(acc[i][n][1]),
                          "+f"(acc[i][n][2]), "+f"(acc[i][n][3])
                        : "r"(af[i].x), "r"(af[i].y), "r"(af[i].z), "r"(af[i].w),
                          "r"(bf[n][0]), "r"(bf[n][1]));
                }
        }
    }

    if (tid < 64) { cs[tid] = 0.f; cs2[tid] = 0.f; }
    __syncthreads();
#pragma unroll
    for (int n = 0; n < 8; n++) {
        float s0 = 0.f, q0 = 0.f, s1 = 0.f, q1 = 0.f;
#pragma unroll
        for (int i = 0; i < 4; i++) {
            float a = acc[i][n][0], b2 = acc[i][n][2];
            s0 += a + b2; q0 += a * a + b2 * b2;
            float c1 = acc[i][n][1], d1 = acc[i][n][3];
            s1 += c1 + d1; q1 += c1 * c1 + d1 * d1;
        }
        s0 += __shfl_xor_sync(0xffffffffu, s0, 4);
        s0 += __shfl_xor_sync(0xffffffffu, s0, 8);
        s0 += __shfl_xor_sync(0xffffffffu, s0, 16);
        q0 += __shfl_xor_sync(0xffffffffu, q0, 4);
        q0 += __shfl_xor_sync(0xffffffffu, q0, 8);
        q0 += __shfl_xor_sync(0xffffffffu, q0, 16);
        s1 += __shfl_xor_sync(0xffffffffu, s1, 4);
        s1 += __shfl_xor_sync(0xffffffffu, s1, 8);
        s1 += __shfl_xor_sync(0xffffffffu, s1, 16);
        q1 += __shfl_xor_sync(0xffffffffu, q1, 4);
        q1 += __shfl_xor_sync(0xffffffffu, q1, 8);
        q1 += __shfl_xor_sync(0xffffffffu, q1, 16);
        if (gid == 0) {
            int c0 = n * 8 + 2 * tq;
            atomicAdd(&cs[c0], s0);  atomicAdd(&cs2[c0], q0);
            atomicAdd(&cs[c0 + 1], s1); atomicAdd(&cs2[c0 + 1], q1);
        }
    }
    __syncthreads();
    if (tid < 64) {
        float mean = cs[tid] * (1.0f / CDIM);
        float var  = cs2[tid] * (1.0f / CDIM) - mean * mean;
        cmean[tid] = mean;
        cinv[tid]  = rsqrtf(var + 1e-5f);
    }
    __syncthreads();

    float gm = gamma[0];
    size_t obase = (size_t)blockIdx.z * CDIM * HW;
#pragma unroll
    for (int i = 0; i < 4; i++) {
        int r = wm * 64 + i * 16 + gid;
        float g0 = gw[r], b0 = bw[r];
        float g1 = gw[r + 8], b1 = bw[r + 8];
#pragma unroll
        for (int n = 0; n < 8; n++) {
            int c = n * 8 + 2 * tq;
            int cg = n0 + c;
            float m0c = cmean[c], i0c = cinv[c];
            float m1c = cmean[c + 1], i1c = cinv[c + 1];
            float2 q0 = *(const float2*)(qsrc + obase + (size_t)r * HW + cg);
            float2 q1 = *(const float2*)(qsrc + obase + (size_t)(r + 8) * HW + cg);
            float2 o0, o1;
            o0.x = gm * ((acc[i][n][0] - m0c) * i0c * g0 + b0) + q0.x;
            o0.y = gm * ((acc[i][n][1] - m1c) * i1c * g0 + b0) + q0.y;
            o1.x = gm * ((acc[i][n][2] - m0c) * i0c * g1 + b1) + q1.x;
            o1.y = gm * ((acc[i][n][3] - m1c) * i1c * g1 + b1) + q1.y;
            *(float2*)(outp + obase + (size_t)r * HW + cg)       = o0;
            *(float2*)(outp + obase + (size_t)(r + 8) * HW + cg) = o1;
        }
    }
}

// ---------------- launch ----------------------------------------------------
extern "C" void kernel_launch(void* const* d_in, const int* in_sizes, int n_in,
                              void* d_out, int out_size) {
    const float* query_source = (const float*)d_in[0];
    const float* context      = (const float*)d_in[1];
    const float* cn_g = (const float*)d_in[2];
    const float* cn_b = (const float*)d_in[3];
    const float* qn_g = (const float*)d_in[4];
    const float* qn_b = (const float*)d_in[5];
    const float* on_g = (const float*)d_in[6];
    const float* on_b = (const float*)d_in[7];
    const float* w_kv  = (const float*)d_in[8];
    const float* w_q   = (const float*)d_in[9];
    const float* w_out = (const float*)d_in[10];
    const float* gamma = (const float*)d_in[11];
    float* out = (float*)d_out;

    dim3 lnb(32, 8);
    const int attn_smem = ATTN_SMEM_FLOATS * 4;
    cudaFuncSetAttribute(attn_mma_kernel,
                         cudaFuncAttributeMaxDynamicSharedMemorySize, attn_smem);
    cudaFuncSetAttribute(wout_final_kernel,
                         cudaFuncAttributeMaxDynamicSharedMemorySize, WF_SMEM_BYTES);
    cudaFuncSetAttribute(kvsel_kernel,
                         cudaFuncAttributeMaxDynamicSharedMemorySize, KVSEL_SMEM_BYTES);

    zero_kernel<<<1024, 256>>>();
    prep_w<<<384, 256>>>(w_kv, w_q, w_out);
    ln_kernel<<<2048, lnb>>>(context, query_source, cn_g, cn_b, qn_g, qn_b);

    tgemm_kernel<<<dim3(32, 8, 8), 128>>>();   // K-stats (no store) + q

    score_kernel<<<64, 64>>>();
    kvsel_kernel<<<dim3(64, 2), 256, KVSEL_SMEM_BYTES>>>(w_kv);

    attn_mma_kernel<<<dim3(32, 64), 128, attn_smem>>>();

    wout_final_kernel<<<dim3(64, 1, 8), 128, WF_SMEM_BYTES>>>(
        query_source, on_g, on_b, gamma, out);
}

// round 17
// speedup vs baseline: 1.0724x; 1.0155x over previous
#include <cuda_runtime.h>
#include <math.h>
#include <stdint.h>

#define HW    4096
#define CDIM  256
#define BATCH 8
#define NBH   64     // B*HEADS
#define DH    64     // DIM_HEAD

// ---------------- scratch (device globals; no runtime allocation) ----------
__device__ float g_ctx[BATCH * CDIM * HW];        // layernormed context (tf32-rounded)
__device__ float g_qs [BATCH * CDIM * HW];        // layernormed query_source (tf32-rounded)
__device__ float g_q  [BATCH * 512  * HW];        // w_q output (l2-normalized)
__device__ float g_att[BATCH * 512  * HW];        // attention output (tf32-rounded)
__device__ float g_qprobe[NBH * DH];
__device__ float g_rowabs[NBH * DH * 64];         // [bh][d][h]
__device__ float g_colabs[NBH * DH * 64];         // [bh][d][w]
__device__ int   g_idxh[NBH * 8];
__device__ int   g_idxw[NBH * 8];
__device__ float g_kselT[NBH * 64 * DH];          // [bh][d][j]  (K^T for mma)
__device__ float g_vsel [NBH * 64 * DH];          // [bh][j][d]

// tf32-pre-rounded weights, packed in mma-fragment order:
// [mtile128][kt16][mblk16][ks8][lane32] -> float4 {A[m][k],A[m+8][k],A[m][k+4],A[m+8][k+4]}
__device__ float g_wkvp[512 * 256];               // K half only
__device__ float g_wqp [512 * 256];
__device__ float g_woutp[256 * 512];

__device__ __forceinline__ float tf32r(float x) {
    uint32_t u;
    asm("cvt.rna.tf32.f32 %0, %1;" : "=r"(u) : "f"(x));
    return __uint_as_float(u);
}

// ---------------- zero scratch reductions ----------------------------------
__global__ void zero_kernel() {
    int i = blockIdx.x * 256 + threadIdx.x;
    if (i < NBH * DH) g_qprobe[i] = 0.f;
    if (i < NBH * DH * 64) { g_rowabs[i] = 0.f; g_colabs[i] = 0.f; }
}

// ---------------- weight prep: tf32-round + pack into fragment order -------
__global__ void prep_w(const float* __restrict__ wkv,
                       const float* __restrict__ wq,
                       const float* __restrict__ wout) {
    int fid = blockIdx.x * 256 + threadIdx.x;
    const float* W; float4* Dst; int K, rel;
    if (fid < 32768)      { W = wkv;  Dst = (float4*)g_wkvp;  K = 256; rel = fid; }
    else if (fid < 65536) { W = wq;   Dst = (float4*)g_wqp;   K = 256; rel = fid - 32768; }
    else                  { W = wout; Dst = (float4*)g_woutp; K = 512; rel = fid - 65536; }
    int KT = K >> 4;
    int per_mtile = KT * 512;
    int mtile = rel / per_mtile;
    int r2 = rel - mtile * per_mtile;
    int kt = r2 >> 9;
    int sub = r2 & 511;
    int mblk = (sub >> 6) & 7;
    int ks = (sub >> 5) & 1;
    int lane = sub & 31;
    int gid = lane >> 2, tq = lane & 3;
    int m = mtile * 128 + mblk * 16 + gid;
    int k = kt * 16 + ks * 8 + tq;
    float4 v;
    v.x = tf32r(W[(size_t)m * K + k]);
    v.y = tf32r(W[(size_t)(m + 8) * K + k]);
    v.z = tf32r(W[(size_t)m * K + k + 4]);
    v.w = tf32r(W[(size_t)(m + 8) * K + k + 4]);
    Dst[rel] = v;
}

// ---------------- channel layernorm, both tensors in one launch ------------
__global__ void ln_kernel(const float* __restrict__ xc,
                          const float* __restrict__ xq,
                          const float* __restrict__ cg, const float* __restrict__ cb,
                          const float* __restrict__ qg, const float* __restrict__ qb) {
    int sel = blockIdx.x >> 10;
    const float* x  = sel ? xq : xc;
    const float* gw = sel ? qg : cg;
    const float* bw = sel ? qb : cb;
    float* out = sel ? g_qs : g_ctx;
    int tx = threadIdx.x, ty = threadIdx.y;
    int gp = (blockIdx.x & 1023) * 32 + tx;
    int bidx = gp >> 12;
    int p = gp & (HW - 1);
    size_t base = (size_t)bidx * CDIM * HW + p;

    float vals[32];
    float s = 0.f, s2 = 0.f;
#pragma unroll
    for (int i = 0; i < 32; i++) {
        int c = ty + i * 8;
        float v = x[base + (size_t)c * HW];
        vals[i] = v; s += v; s2 += v * v;
    }
    __shared__ float rs[8][32], rs2[8][32];
    rs[ty][tx] = s; rs2[ty][tx] = s2;
    __syncthreads();
    for (int st = 4; st > 0; st >>= 1) {
        if (ty < st) { rs[ty][tx] += rs[ty + st][tx]; rs2[ty][tx] += rs2[ty + st][tx]; }
        __syncthreads();
    }
    float mean = rs[0][tx] * (1.0f / CDIM);
    float var  = rs2[0][tx] * (1.0f / CDIM) - mean * mean;
    float inv  = rsqrtf(var + 1e-5f);
#pragma unroll
    for (int i = 0; i < 32; i++) {
        int c = ty + i * 8;
        out[base + (size_t)c * HW] = tf32r((vals[i] - mean) * inv * gw[c] + bw[c]);
    }
}

// ---------------- cp.async helpers -----------------------------------------
__device__ __forceinline__ void cpasync16(uint32_t smem, const void* g) {
    asm volatile("cp.async.cg.shared.global [%0], [%1], 16;\n" :: "r"(smem), "l"(g));
}
#define CP_COMMIT() asm volatile("cp.async.commit_group;\n" ::: "memory")
#define CP_WAIT1()  asm volatile("cp.async.wait_group 1;\n" ::: "memory")
#define CP_WAIT2()  asm volatile("cp.async.wait_group 2;\n" ::: "memory")

// ---------------- tensor-core GEMM: K-stats (no store) + q -----------------
// grid (32, 8, 8): y<4 -> K stats tile y (NO output store), y>=4 -> q tile.
// 128 threads / 4 warps (2x2), 64x64 warp tiles, 4-stage pipeline,
// both-ks fragments batched ahead of the MMA burst.
#define BS_STRIDE 136

__global__ void __launch_bounds__(128, 2)
tgemm_kernel() {
    int by = blockIdx.y;
    int selEff;
    if (by < 4) selEff = 0;
    else { selEff = 1; by -= 4; }
    const uint4* Ap4; const float* Bp; float* Cp;
    if (selEff == 0) { Ap4 = (const uint4*)g_wkvp; Bp = g_ctx; Cp = nullptr; }
    else             { Ap4 = (const uint4*)g_wqp;  Bp = g_qs;  Cp = g_q;   }
    const int KT = 16;
    const int K = 256;
    Bp += (size_t)blockIdx.z * K * HW;
    if (Cp) Cp += (size_t)blockIdx.z * 512 * HW;
    Ap4 += (size_t)by * (KT * 512);

    __shared__ __align__(16) uint4 As4[4][512];
    __shared__ __align__(16) float Bs[4][16][BS_STRIDE];

    int m0 = by * 128, n0 = blockIdx.x * 128;
    int tid = threadIdx.x;
    int wid = tid >> 5, lane = tid & 31;
    int wm = wid >> 1, wn = wid & 1;
    int gid = lane >> 2, tq = lane & 3;

    int bk = tid >> 3;
    int bn = (tid & 7) * 16;

    auto load_stage = [&](int s, int kt) {
#pragma unroll
        for (int r = 0; r < 4; r++) {
            uint32_t adst = (uint32_t)__cvta_generic_to_shared(&As4[s][tid + r * 128]);
            cpasync16(adst, Ap4 + kt * 512 + tid + r * 128);
        }
        uint32_t bdst = (uint32_t)__cvta_generic_to_shared(&Bs[s][bk][bn]);
        const float* bsrc = Bp + (size_t)(kt * 16 + bk) * HW + n0 + bn;
#pragma unroll
        for (int r = 0; r < 4; r++)
            cpasync16(bdst + r * 16, bsrc + r * 4);
    };

    float acc[4][8][4];
#pragma unroll
    for (int i = 0; i < 4; i++)
#pragma unroll
        for (int n = 0; n < 8; n++)
#pragma unroll
            for (int r = 0; r < 4; r++) acc[i][n][r] = 0.f;

    load_stage(0, 0); CP_COMMIT();
    load_stage(1, 1); CP_COMMIT();
    load_stage(2, 2); CP_COMMIT();

    for (int kt = 0; kt < KT; kt++) {
        CP_WAIT2();
        __syncthreads();
        if (kt + 3 < KT) load_stage((kt + 3) & 3, kt + 3);
        CP_COMMIT();
        int s = kt & 3;

        uint4 af2[2][4];
        uint32_t bf2[2][8][2];
#pragma unroll
        for (int ks = 0; ks < 2; ks++) {
            int kk = ks * 8 + tq;
#pragma unroll
            for (int i = 0; i < 4; i++)
                af2[ks][i] = As4[s][(4 * wm + i) * 64 + ks * 32 + lane];
#pragma unroll
            for (int n = 0; n < 8; n++) {
                int c = wn * 64 + n * 8 + gid;
                bf2[ks][n][0] = __float_as_uint(Bs[s][kk][c]);
                bf2[ks][n][1] = __float_as_uint(Bs[s][kk + 4][c]);
            }
        }
#pragma unroll
        for (int ks = 0; ks < 2; ks++)
#pragma unroll
            for (int i = 0; i < 4; i++)
#pragma unroll
                for (int n = 0; n < 8; n++) {
                    asm volatile(
                        "mma.sync.aligned.m16n8k8.row.col.f32.tf32.tf32.f32 "
                        "{%0,%1,%2,%3}, {%4,%5,%6,%7}, {%8,%9}, {%0,%1,%2,%3};"
                        : "+f"(acc[i][n][0]), "+f"(acc[i][n][1]),
                          "+f"(acc[i][n][2]), "+f"(acc[i][n][3])
                        : "r"(af2[ks][i].x), "r"(af2[ks][i].y),
                          "r"(af2[ks][i].z), "r"(af2[ks][i].w),
                          "r"(bf2[ks][n][0]), "r"(bf2[ks][n][1]));
                }
    }

    float inv_c[8][2];
#pragma unroll
    for (int n = 0; n < 8; n++) {
        float s0 = 0.f, s1 = 0.f;
#pragma unroll
        for (int i = 0; i < 4; i++) {
            s0 += acc[i][n][0] * acc[i][n][0] + acc[i][n][2] * acc[i][n][2];
            s1 += acc[i][n][1] * acc[i][n][1] + acc[i][n][3] * acc[i][n][3];
        }
        s0 += __shfl_xor_sync(0xffffffffu, s0, 4);
        s0 += __shfl_xor_sync(0xffffffffu, s0, 8);
        s0 += __shfl_xor_sync(0xffffffffu, s0, 16);
        s1 += __shfl_xor_sync(0xffffffffu, s1, 4);
        s1 += __shfl_xor_sync(0xffffffffu, s1, 8);
        s1 += __shfl_xor_sync(0xffffffffu, s1, 16);
        inv_c[n][0] = 1.0f / fmaxf(sqrtf(s0), 1e-12f);
        inv_c[n][1] = 1.0f / fmaxf(sqrtf(s1), 1e-12f);
    }
#pragma unroll
    for (int i = 0; i < 4; i++)
#pragma unroll
        for (int n = 0; n < 8; n++) {
            acc[i][n][0] *= inv_c[n][0];
            acc[i][n][1] *= inv_c[n][1];
            acc[i][n][2] *= inv_c[n][0];
            acc[i][n][3] *= inv_c[n][1];
        }

    int head = by * 2 + wm;
    int bh = blockIdx.z * 8 + head;

    if (selEff == 1) {
#pragma unroll
        for (int i = 0; i < 4; i++) {
            float r0s = 0.f, r1s = 0.f;
#pragma unroll
            for (int n = 0; n < 8; n++) {
                r0s += acc[i][n][0] + acc[i][n][1];
                r1s += acc[i][n][2] + acc[i][n][3];
            }
            r0s += __shfl_xor_sync(0xffffffffu, r0s, 1);
            r0s += __shfl_xor_sync(0xffffffffu, r0s, 2);
            r1s += __shfl_xor_sync(0xffffffffu, r1s, 1);
            r1s += __shfl_xor_sync(0xffffffffu, r1s, 2);
            if (tq == 0) {
                atomicAdd(&g_qprobe[bh * 64 + i * 16 + gid], r0s);
                atomicAdd(&g_qprobe[bh * 64 + i * 16 + gid + 8], r1s);
            }
        }
#pragma unroll
        for (int i = 0; i < 4; i++) {
            int r = m0 + wm * 64 + i * 16 + gid;
#pragma unroll
            for (int n = 0; n < 8; n++) {
                int c = n0 + wn * 64 + n * 8 + 2 * tq;
                *(float2*)(Cp + (size_t)r * HW + c)       = make_float2(acc[i][n][0], acc[i][n][1]);
                *(float2*)(Cp + (size_t)(r + 8) * HW + c) = make_float2(acc[i][n][2], acc[i][n][3]);
            }
        }
    } else {
        int hrow = blockIdx.x * 2 + wn;
#pragma unroll
        for (int i = 0; i < 4; i++) {
            int d0 = i * 16 + gid;
            float r0s = 0.f, r1s = 0.f;
#pragma unroll
            for (int n = 0; n < 8; n++) {
                float a0 = fabsf(acc[i][n][0]), a1 = fabsf(acc[i][n][1]);
                float a2 = fabsf(acc[i][n][2]), a3 = fabsf(acc[i][n][3]);
                r0s += a0 + a1; r1s += a2 + a3;
                int w0 = n * 8 + 2 * tq;
                atomicAdd(&g_colabs[bh * 4096 + d0 * 64 + w0],           a0);
                atomicAdd(&g_colabs[bh * 4096 + d0 * 64 + w0 + 1],       a1);
                atomicAdd(&g_colabs[bh * 4096 + (d0 + 8) * 64 + w0],     a2);
                atomicAdd(&g_colabs[bh * 4096 + (d0 + 8) * 64 + w0 + 1], a3);
            }
            r0s += __shfl_xor_sync(0xffffffffu, r0s, 1);
            r0s += __shfl_xor_sync(0xffffffffu, r0s, 2);
            r1s += __shfl_xor_sync(0xffffffffu, r1s, 1);
            r1s += __shfl_xor_sync(0xffffffffu, r1s, 2);
            if (tq == 0) {
                atomicAdd(&g_rowabs[bh * 4096 + d0 * 64 + hrow],       r0s);
                atomicAdd(&g_rowabs[bh * 4096 + (d0 + 8) * 64 + hrow], r1s);
            }
        }
    }
}

// ---------------- scores + top-8 selection ---------------------------------
__global__ void score_kernel() {
    int bh = blockIdx.x;
    int t = threadIdx.x;
    __shared__ float qp[64], sc[64];
    qp[t] = g_qprobe[bh * 64 + t];
    __syncthreads();

    float s = 0.f;
    for (int d = 0; d < 64; d++) s += qp[d] * g_rowabs[bh * 4096 + d * 64 + t];
    sc[t] = s;
    __syncthreads();
    if (t == 0) {
        for (int it = 0; it < 8; it++) {
            int best = 0; float bv = sc[0];
            for (int h = 1; h < 64; h++) if (sc[h] > bv) { bv = sc[h]; best = h; }
            g_idxh[bh * 8 + it] = best; sc[best] = -3e38f;
        }
    }
    __syncthreads();

    float s2 = 0.f;
    for (int d = 0; d < 64; d++) s2 += qp[d] * g_colabs[bh * 4096 + d * 64 + t];
    sc[t] = s2;
    __syncthreads();
    if (t == 0) {
        for (int it = 0; it < 8; it++) {
            int best = 0; float bv = sc[0];
            for (int w = 1; w < 64; w++) if (sc[w] > bv) { bv = sc[w]; best = w; }
            g_idxw[bh * 8 + it] = best; sc[best] = -3e38f;
        }
    }
}

// ---------------- K/V at selected pixels (fp32, smem-staged) ---------------
#define KV_C_ST 257
#define KV_W_ST 68
#define KVSEL_SMEM_BYTES ((64 * KV_C_ST + 256 * KV_W_ST) * 4)

__global__ void __launch_bounds__(256)
kvsel_kernel(const float* __restrict__ wkv) {
    extern __shared__ float ksm[];
    float* csm = ksm;
    float* wsm = ksm + 64 * KV_C_ST;
    __shared__ int pix[64];

    int bh = blockIdx.x, isV = blockIdx.y;
    int b = bh >> 3, head = bh & 7;
    int t = threadIdx.x;
    if (t < 64) pix[t] = g_idxh[bh * 8 + (t >> 3)] * 64 + g_idxw[bh * 8 + (t & 7)];
    __syncthreads();

    const float* wv = wkv + (size_t)(isV * 512 + head * 64) * 256;
#pragma unroll 4
    for (int it = 0; it < 64; it++) {
        int idx = it * 256 + t;
        int d = idx >> 8, c = idx & 255;
        wsm[c * KV_W_ST + d] = wv[d * 256 + c];
    }
    const float* ctx = g_ctx + (size_t)b * CDIM * HW;
#pragma unroll 4
    for (int it = 0; it < 64; it++) {
        int idx = it * 256 + t;
        int j = idx >> 8, c = idx & 255;
        csm[j * KV_C_ST + c] = __ldg(ctx + (size_t)c * HW + pix[j]);
    }
    __syncthreads();

    int j = t >> 2, dq = t & 3;
    float acc[16];
#pragma unroll
    for (int i = 0; i < 16; i++) acc[i] = 0.f;
    const float* crow = csm + j * KV_C_ST;
#pragma unroll 4
    for (int c = 0; c < 256; c++) {
        float xv = crow[c];
        const float4* wr = (const float4*)(wsm + c * KV_W_ST + dq * 16);
        float4 w0 = wr[0], w1 = wr[1], w2 = wr[2], w3 = wr[3];
        acc[0]  += w0.x * xv; acc[1]  += w0.y * xv; acc[2]  += w0.z * xv; acc[3]  += w0.w * xv;
        acc[4]  += w1.x * xv; acc[5]  += w1.y * xv; acc[6]  += w1.z * xv; acc[7]  += w1.w * xv;
        acc[8]  += w2.x * xv; acc[9]  += w2.y * xv; acc[10] += w2.z * xv; acc[11] += w2.w * xv;
        acc[12] += w3.x * xv; acc[13] += w3.y * xv; acc[14] += w3.z * xv; acc[15] += w3.w * xv;
    }

    if (isV) {
#pragma unroll
        for (int i = 0; i < 16; i++)
            g_vsel[bh * 4096 + j * 64 + dq * 16 + i] = acc[i];
    } else {
        float s = 0.f;
#pragma unroll
        for (int i = 0; i < 16; i++) s += acc[i] * acc[i];
        s += __shfl_xor_sync(0xffffffffu, s, 1);
        s += __shfl_xor_sync(0xffffffffu, s, 2);
        float inv = 1.0f / fmaxf(sqrtf(s), 1e-12f);
#pragma unroll
        for (int i = 0; i < 16; i++)
            g_kselT[bh * 4096 + (dq * 16 + i) * 64 + j] = acc[i] * inv;
    }
}

// ---------------- tensor-core attention (k-pair batched fragments) ---------
#define KT_ST 72
#define QS_ST 136
#define PS_ST 68
#define ATTN_SMEM_FLOATS (4608 + 4608 + 8704)

__global__ void __launch_bounds__(128)
attn_mma_kernel() {
    extern __shared__ float sm[];
    float* kst = sm;
    float* vs  = sm + 4608;
    float* qps = sm + 9216;

    int bh = blockIdx.y;
    int pix0 = blockIdx.x * 128;
    int tid = threadIdx.x, lane = tid & 31, w = tid >> 5;
    int gid = lane >> 2, tq = lane & 3;
    int m0w = w * 32;
    size_t qb = (size_t)bh * 64 * HW + pix0;

    for (int t = tid; t < 4096; t += 128) {
        int r = t >> 6, c = t & 63;
        kst[r * KT_ST + c] = tf32r(g_kselT[bh * 4096 + t]);
        vs [r * KT_ST + c] = tf32r(g_vsel [bh * 4096 + t]);
    }
    for (int r = 0; r < 64; r += 2) {
        int rr = r + (tid >> 6);
        int cc = tid & 63;
        qps[rr * QS_ST + cc]      = tf32r(g_q[qb + (size_t)rr * HW + cc]);
        qps[rr * QS_ST + cc + 64] = tf32r(g_q[qb + (size_t)rr * HW + cc + 64]);
    }
    __syncthreads();

    float accs[2][8][4];
#pragma unroll
    for (int i = 0; i < 2; i++)
#pragma unroll
        for (int n = 0; n < 8; n++)
#pragma unroll
            for (int r = 0; r < 4; r++) accs[i][n][r] = 0.f;

#pragma unroll
    for (int kp = 0; kp < 4; kp++) {
        uint32_t a2[2][2][4], b2[2][8][2];
#pragma unroll
        for (int h = 0; h < 2; h++) {
            int kk = (kp * 2 + h) * 8;
#pragma unroll
            for (int i = 0; i < 2; i++) {
                int mc = m0w + i * 16 + gid;
                a2[h][i][0] = __float_as_uint(qps[(kk + tq) * QS_ST + mc]);
                a2[h][i][1] = __float_as_uint(qps[(kk + tq) * QS_ST + mc + 8]);
                a2[h][i][2] = __float_as_uint(qps[(kk + tq + 4) * QS_ST + mc]);
                a2[h][i][3] = __float_as_uint(qps[(kk + tq + 4) * QS_ST + mc + 8]);
            }
#pragma unroll
            for (int n = 0; n < 8; n++) {
                b2[h][n][0] = __float_as_uint(kst[(kk + tq) * KT_ST + n * 8 + gid]);
                b2[h][n][1] = __float_as_uint(kst[(kk + tq + 4) * KT_ST + n * 8 + gid]);
            }
        }
#pragma unroll
        for (int h = 0; h < 2; h++)
#pragma unroll
            for (int i = 0; i < 2; i++)
#pragma unroll
                for (int n = 0; n < 8; n++)
                    asm volatile(
                        "mma.sync.aligned.m16n8k8.row.col.f32.tf32.tf32.f32 "
                        "{%0,%1,%2,%3}, {%4,%5,%6,%7}, {%8,%9}, {%0,%1,%2,%3};"
                        : "+f"(accs[i][n][0]), "+f"(accs[i][n][1]),
                          "+f"(accs[i][n][2]), "+f"(accs[i][n][3])
                        : "r"(a2[h][i][0]), "r"(a2[h][i][1]),
                          "r"(a2[h][i][2]), "r"(a2[h][i][3]),
                          "r"(b2[h][n][0]), "r"(b2[h][n][1]));
    }

    float inv0[2], inv1[2];
#pragma unroll
    for (int i = 0; i < 2; i++) {
        float mx0 = -3e38f, mx1 = -3e38f;
#pragma unroll
        for (int n = 0; n < 8; n++) {
            mx0 = fmaxf(mx0, fmaxf(accs[i][n][0], accs[i][n][1]));
            mx1 = fmaxf(mx1, fmaxf(accs[i][n][2], accs[i][n][3]));
        }
        mx0 = fmaxf(mx0, __shfl_xor_sync(0xffffffffu, mx0, 1));
        mx0 = fmaxf(mx0, __shfl_xor_sync(0xffffffffu, mx0, 2));
        mx1 = fmaxf(mx1, __shfl_xor_sync(0xffffffffu, mx1, 1));
        mx1 = fmaxf(mx1, __shfl_xor_sync(0xffffffffu, mx1, 2));
        float s0 = 0.f, s1 = 0.f;
#pragma unroll
        for (int n = 0; n < 8; n++) {
            accs[i][n][0] = __expf(accs[i][n][0] - mx0);
            accs[i][n][1] = __expf(accs[i][n][1] - mx0);
            accs[i][n][2] = __expf(accs[i][n][2] - mx1);
            accs[i][n][3] = __expf(accs[i][n][3] - mx1);
            s0 += accs[i][n][0] + accs[i][n][1];
            s1 += accs[i][n][2] + accs[i][n][3];
        }
        s0 += __shfl_xor_sync(0xffffffffu, s0, 1);
        s0 += __shfl_xor_sync(0xffffffffu, s0, 2);
        s1 += __shfl_xor_sync(0xffffffffu, s1, 1);
        s1 += __shfl_xor_sync(0xffffffffu, s1, 2);
        inv0[i] = 1.0f / s0;
        inv1[i] = 1.0f / s1;
    }

    __syncthreads();
    float* ps = qps;
#pragma unroll
    for (int i = 0; i < 2; i++) {
        int r0 = m0w + i * 16 + gid;
#pragma unroll
        for (int n = 0; n < 8; n++) {
            int c = n * 8 + 2 * tq;
            ps[r0 * PS_ST + c]           = tf32r(accs[i][n][0]);
            ps[r0 * PS_ST + c + 1]       = tf32r(accs[i][n][1]);
            ps[(r0 + 8) * PS_ST + c]     = tf32r(accs[i][n][2]);
            ps[(r0 + 8) * PS_ST + c + 1] = tf32r(accs[i][n][3]);
        }
    }

    float acco[2][8][4];
#pragma unroll
    for (int i = 0; i < 2; i++)
#pragma unroll
        for (int n = 0; n < 8; n++)
#pragma unroll
            for (int r = 0; r < 4; r++) acco[i][n][r] = 0.f;

#pragma unroll
    for (int kp = 0; kp < 4; kp++) {
        uint32_t a2[2][2][4], b2[2][8][2];
#pragma unroll
        for (int h = 0; h < 2; h++) {
            int kk = (kp * 2 + h) * 8;
#pragma unroll
            for (int i = 0; i < 2; i++) {
                int r0 = m0w + i * 16 + gid;
                a2[h][i][0] = __float_as_uint(ps[r0 * PS_ST + kk + tq]);
                a2[h][i][1] = __float_as_uint(ps[(r0 + 8) * PS_ST + kk + tq]);
                a2[h][i][2] = __float_as_uint(ps[r0 * PS_ST + kk + tq + 4]);
                a2[h][i][3] = __float_as_uint(ps[(r0 + 8) * PS_ST + kk + tq + 4]);
            }
#pragma unroll
            for (int n = 0; n < 8; n++) {
                b2[h][n][0] = __float_as_uint(vs[(kk + tq) * KT_ST + n * 8 + gid]);
                b2[h][n][1] = __float_as_uint(vs[(kk + tq + 4) * KT_ST + n * 8 + gid]);
            }
        }
#pragma unroll
        for (int h = 0; h < 2; h++)
#pragma unroll
            for (int i = 0; i < 2; i++)
#pragma unroll
                for (int n = 0; n < 8; n++)
                    asm volatile(
                        "mma.sync.aligned.m16n8k8.row.col.f32.tf32.tf32.f32 "
                        "{%0,%1,%2,%3}, {%4,%5,%6,%7}, {%8,%9}, {%0,%1,%2,%3};"
                        : "+f"(acco[i][n][0]), "+f"(acco[i][n][1]),
                          "+f"(acco[i][n][2]), "+f"(acco[i][n][3])
                        : "r"(a2[h][i][0]), "r"(a2[h][i][1]),
                          "r"(a2[h][i][2]), "r"(a2[h][i][3]),
                          "r"(b2[h][n][0]), "r"(b2[h][n][1]));
    }

    size_t ob = (size_t)bh * 64 * HW + pix0;
#pragma unroll
    for (int i = 0; i < 2; i++) {
        int prow = m0w + i * 16 + gid;
#pragma unroll
        for (int n = 0; n < 8; n++) {
            int d0 = n * 8 + 2 * tq;
            g_att[ob + (size_t)d0 * HW + prow]           = tf32r(acco[i][n][0] * inv0[i]);
            g_att[ob + (size_t)(d0 + 1) * HW + prow]     = tf32r(acco[i][n][1] * inv0[i]);
            g_att[ob + (size_t)d0 * HW + prow + 8]       = tf32r(acco[i][n][2] * inv1[i]);
            g_att[ob + (size_t)(d0 + 1) * HW + prow + 8] = tf32r(acco[i][n][3] * inv1[i]);
        }
    }
}

// ---------------- w_out GEMM + final LN + residual (128 thr, 3-stage) ------
// Both-ks fragment batching; occupancy 2 for register headroom.
#define WF_BS_ST 72
#define WF_A_STAGE 1024
#define WF_AS_BYTES (3 * WF_A_STAGE * 16)
#define WF_BS_BYTES (3 * 16 * WF_BS_ST * 4)
#define WF_SMEM_BYTES (WF_AS_BYTES + WF_BS_BYTES + 4 * 64 * 4)

__global__ void __launch_bounds__(128, 2)
wout_final_kernel(const float* __restrict__ qsrc,
                  const float* __restrict__ gw,
                  const float* __restrict__ bw,
                  const float* __restrict__ gamma,
                  float* __restrict__ outp) {
    extern __shared__ char dsm[];
    uint4* As4 = (uint4*)dsm;
    float* Bs  = (float*)(dsm + WF_AS_BYTES);
    float* cs    = (float*)(dsm + WF_AS_BYTES + WF_BS_BYTES);
    float* cs2   = cs + 64;
    float* cmean = cs2 + 64;
    float* cinv  = cmean + 64;

    const uint4* Ap4 = (const uint4*)g_woutp;
    const float* Bp = g_att + (size_t)blockIdx.z * 512 * HW;
    int n0 = blockIdx.x * 64;
    int tid = threadIdx.x, lane = tid & 31;
    int wm = tid >> 5;
    int gid = lane >> 2, tq = lane & 3;

    int bk = tid >> 3;
    int bn = (tid & 7) * 8;

    auto load_stage = [&](int s, int kt) {
#pragma unroll
        for (int r = 0; r < 8; r++) {
            int idx = r * 128 + tid;
            int mt = idx >> 9, sub = idx & 511;
            uint32_t adst = (uint32_t)__cvta_generic_to_shared(&As4[s * WF_A_STAGE + idx]);
            cpasync16(adst, Ap4 + (size_t)mt * (32 * 512) + kt * 512 + sub);
        }
        uint32_t bdst = (uint32_t)__cvta_generic_to_shared(&Bs[(s * 16 + bk) * WF_BS_ST + bn]);
        const float* bsrc = Bp + (size_t)(kt * 16 + bk) * HW + n0 + bn;
        cpasync16(bdst, bsrc);
        cpasync16(bdst + 16, bsrc + 4);
    };

    float acc[4][8][4];
#pragma unroll
    for (int i = 0; i < 4; i++)
#pragma unroll
        for (int n = 0; n < 8; n++)
#pragma unroll
            for (int r = 0; r < 4; r++) acc[i][n][r] = 0.f;

    load_stage(0, 0); CP_COMMIT();
    load_stage(1, 1); CP_COMMIT();

    int mt = wm >> 1, mbb = (wm & 1) * 4;
    for (int kt = 0; kt < 32; kt++) {
        CP_WAIT1();
        __syncthreads();
        if (kt + 2 < 32) load_stage((kt + 2) % 3, kt + 2);
        CP_COMMIT();
        int s = kt % 3;

        uint4 af2[2][4];
        uint32_t bf2[2][8][2];
#pragma unroll
        for (int ks = 0; ks < 2; ks++) {
            int kk = ks * 8 + tq;
#pragma unroll
            for (int i = 0; i < 4; i++)
                af2[ks][i] = As4[s * WF_A_STAGE + mt * 512 + (mbb + i) * 64 + ks * 32 + lane];
#pragma unroll
            for (int n = 0; n < 8; n++) {
                int c = n * 8 + gid;
                bf2[ks][n][0] = __float_as_uint(Bs[(s * 16 + kk) * WF_BS_ST + c]);
                bf2[ks][n][1] = __float_as_uint(Bs[(s * 16 + kk + 4) * WF_BS_ST + c]);
            }
        }
#pragma unroll
        for (int ks = 0; ks < 2; ks++)
#pragma unroll
            for (int i = 0; i < 4; i++)
#pragma unroll
                for (int n = 0; n < 8; n++) {
                    asm volatile(
                        "mma.sync.aligned.m16n8k8.row.col.f32.tf32.tf32.f32 "
                        "{%0,%1,%2,%3}, {%4,%5,%6,%7}, {%8,%9}, {%0,%1,%2,%3};"
                        : "+f"(acc[i][n][0]), "+f"(acc[i][n][1]),
                          "+f"(acc[i][n][2]), "+f"(acc[i][n][3])
                        : "r"(af2[ks][i].x), "r"(af2[ks][i].y),
                          "r"(af2[ks][i].z), "r"(af2[ks][i].w),
                          "r"(bf2[ks][n][0]), "r"(bf2[ks][n][1]));
                }
    }

    if (tid < 64) { cs[tid] = 0.f; cs2[tid] = 0.f; }
    __syncthreads();
#pragma unroll
    for (int n = 0; n < 8; n++) {
        float s0 = 0.f, q0 = 0.f, s1 = 0.f, q1 = 0.f;
#pragma unroll
        for (int i = 0; i < 4; i++) {
            float a = acc[i][n][0], b2 = acc[i][n][2];
            s0 += a + b2; q0 += a * a + b2 * b2;
            float c1 = acc[i][n][1], d1 = acc[i][n][3];
            s1 += c1 + d1; q1 += c1 * c1 + d1 * d1;
        }
        s0 += __shfl_xor_sync(0xffffffffu, s0, 4);
        s0 += __shfl_xor_sync(0xffffffffu, s0, 8);
        s0 += __shfl_xor_sync(0xffffffffu, s0, 16);
        q0 += __shfl_xor_sync(0xffffffffu, q0, 4);
        q0 += __shfl_xor_sync(0xffffffffu, q0, 8);
        q0 += __shfl_xor_sync(0xffffffffu, q0, 16);
        s1 += __shfl_xor_sync(0xffffffffu, s1, 4);
        s1 += __shfl_xor_sync(0xffffffffu, s1, 8);
        s1 += __shfl_xor_sync(0xffffffffu, s1, 16);
        q1 += __shfl_xor_sync(0xffffffffu, q1, 4);
        q1 += __shfl_xor_sync(0xffffffffu, q1, 8);
        q1 += __shfl_xor_sync(0xffffffffu, q1, 16);
        if (gid == 0) {
            int c0 = n * 8 + 2 * tq;
            atomicAdd(&cs[c0], s0);  atomicAdd(&cs2[c0], q0);
            atomicAdd(&cs[c0 + 1], s1); atomicAdd(&cs2[c0 + 1], q1);
        }
    }
    __syncthreads();
    if (tid < 64) {
        float mean = cs[tid] * (1.0f / CDIM);
        float var  = cs2[tid] * (1.0f / CDIM) - mean * mean;
        cmean[tid] = mean;
        cinv[tid]  = rsqrtf(var + 1e-5f);
    }
    __syncthreads();

    float gm = gamma[0];
    size_t obase = (size_t)blockIdx.z * CDIM * HW;
#pragma unroll
    for (int i = 0; i < 4; i++) {
        int r = wm * 64 + i * 16 + gid;
        float g0 = gw[r], b0 = bw[r];
        float g1 = gw[r + 8], b1 = bw[r + 8];
#pragma unroll
        for (int n = 0; n < 8; n++) {
            int c = n * 8 + 2 * tq;
            int cg = n0 + c;
            float m0c = cmean[c], i0c = cinv[c];
            float m1c = cmean[c + 1], i1c = cinv[c + 1];
            float2 q0 = *(const float2*)(qsrc + obase + (size_t)r * HW + cg);
            float2 q1 = *(const float2*)(qsrc + obase + (size_t)(r + 8) * HW + cg);
            float2 o0, o1;
            o0.x = gm * ((acc[i][n][0] - m0c) * i0c * g0 + b0) + q0.x;
            o0.y = gm * ((acc[i][n][1] - m1c) * i1c * g0 + b0) + q0.y;
            o1.x = gm * ((acc[i][n][2] - m0c) * i0c * g1 + b1) + q1.x;
            o1.y = gm * ((acc[i][n][3] - m1c) * i1c * g1 + b1) + q1.y;
            *(float2*)(outp + obase + (size_t)r * HW + cg)       = o0;
            *(float2*)(outp + obase + (size_t)(r + 8) * HW + cg) = o1;
        }
    }
}

// ---------------- launch ----------------------------------------------------
extern "C" void kernel_launch(void* const* d_in, const int* in_sizes, int n_in,
                              void* d_out, int out_size) {
    const float* query_source = (const float*)d_in[0];
    const float* context      = (const float*)d_in[1];
    const float* cn_g = (const float*)d_in[2];
    const float* cn_b = (const float*)d_in[3];
    const float* qn_g = (const float*)d_in[4];
    const float* qn_b = (const float*)d_in[5];
    const float* on_g = (const float*)d_in[6];
    const float* on_b = (const float*)d_in[7];
    const float* w_kv  = (const float*)d_in[8];
    const float* w_q   = (const float*)d_in[9];
    const float* w_out = (const float*)d_in[10];
    const float* gamma = (const float*)d_in[11];
    float* out = (float*)d_out;

    dim3 lnb(32, 8);
    const int attn_smem = ATTN_SMEM_FLOATS * 4;
    cudaFuncSetAttribute(attn_mma_kernel,
                         cudaFuncAttributeMaxDynamicSharedMemorySize, attn_smem);
    cudaFuncSetAttribute(wout_final_kernel,
                         cudaFuncAttributeMaxDynamicSharedMemorySize, WF_SMEM_BYTES);
    cudaFuncSetAttribute(kvsel_kernel,
                         cudaFuncAttributeMaxDynamicSharedMemorySize, KVSEL_SMEM_BYTES);

    zero_kernel<<<1024, 256>>>();
    prep_w<<<384, 256>>>(w_kv, w_q, w_out);
    ln_kernel<<<2048, lnb>>>(context, query_source, cn_g, cn_b, qn_g, qn_b);

    tgemm_kernel<<<dim3(32, 8, 8), 128>>>();   // K-stats (no store) + q

    score_kernel<<<64, 64>>>();
    kvsel_kernel<<<dim3(64, 2), 256, KVSEL_SMEM_BYTES>>>(w_kv);

    attn_mma_kernel<<<dim3(32, 64), 128, attn_smem>>>();

    wout_final_kernel<<<dim3(64, 1, 8), 128, WF_SMEM_BYTES>>>(
        query_source, on_g, on_b, gamma, out);
}